// round 1
// baseline (speedup 1.0000x reference)
#include <cuda_runtime.h>
#include <math.h>

#define BATCH 4
#define SEQ   2048
#define DMODEL 1024
#define NHEADS 16
#define HDIM  64
#define MROWS (BATCH*SEQ)   // 8192

// Scratch (no cudaMalloc allowed)
__device__ float g_Q[BATCH*NHEADS*SEQ*HDIM];   // [b,h,t,d]
__device__ float g_K[BATCH*NHEADS*SEQ*HDIM];
__device__ float g_V[BATCH*NHEADS*SEQ*HDIM];
__device__ float g_A[BATCH*SEQ*DMODEL];        // attention out, [b,t,c]

// ---------------------------------------------------------------------------
// GEMM: Y = X @ W + bias.  X:[M,1024] row-major, W:[1024,1024] row-major.
// BM=128, BN=128, BK=8, 256 threads, 8x8 micro-tile per thread.
// OUT_HEADED=1: scatter to [b,h,t,d]; 0: plain [m,n].
// ---------------------------------------------------------------------------
template<int OUT_HEADED>
__global__ __launch_bounds__(256)
void gemm_kernel(const float* __restrict__ X, const float* __restrict__ W,
                 const float* __restrict__ bias, float* __restrict__ Y)
{
    __shared__ float As[8][128];   // transposed A tile
    __shared__ float Bs[8][128];

    const int tid = threadIdx.x;
    const int bn  = blockIdx.x;    // N/128 = 8
    const int bm  = blockIdx.y;    // M/128 = 64
    const int tr  = tid >> 4;      // 0..15
    const int tc  = tid & 15;      // 0..15

    const int arow = tid >> 1;          // 0..127
    const int acol = (tid & 1) * 4;     // 0 or 4
    const int brow = tid >> 5;          // 0..7
    const int bcol = (tid & 31) * 4;    // 0..124

    const float* Xp = X + (size_t)(bm * 128 + arow) * DMODEL + acol;
    const float* Wp = W + (size_t)brow * DMODEL + bn * 128 + bcol;

    float acc[8][8];
    #pragma unroll
    for (int i = 0; i < 8; i++)
        #pragma unroll
        for (int j = 0; j < 8; j++) acc[i][j] = 0.f;

    for (int k0 = 0; k0 < DMODEL; k0 += 8) {
        float4 av = *(const float4*)(Xp + k0);
        float4 bv = *(const float4*)(Wp + (size_t)k0 * DMODEL);
        As[acol + 0][arow] = av.x;
        As[acol + 1][arow] = av.y;
        As[acol + 2][arow] = av.z;
        As[acol + 3][arow] = av.w;
        *(float4*)&Bs[brow][bcol] = bv;
        __syncthreads();

        #pragma unroll
        for (int k = 0; k < 8; k++) {
            float a[8], b[8];
            *(float4*)(a)     = *(const float4*)&As[k][tr * 8];
            *(float4*)(a + 4) = *(const float4*)&As[k][tr * 8 + 4];
            *(float4*)(b)     = *(const float4*)&Bs[k][tc * 8];
            *(float4*)(b + 4) = *(const float4*)&Bs[k][tc * 8 + 4];
            #pragma unroll
            for (int i = 0; i < 8; i++)
                #pragma unroll
                for (int j = 0; j < 8; j++)
                    acc[i][j] = fmaf(a[i], b[j], acc[i][j]);
        }
        __syncthreads();
    }

    #pragma unroll
    for (int i = 0; i < 8; i++) {
        const int m = bm * 128 + tr * 8 + i;
        #pragma unroll
        for (int j = 0; j < 8; j++) {
            const int n = bn * 128 + tc * 8 + j;
            const float v = acc[i][j] + bias[n];
            if (OUT_HEADED) {
                const int b = m >> 11, t = m & 2047;
                const int h = n >> 6,  d = n & 63;
                Y[(((size_t)(b * NHEADS + h) * SEQ) + t) * HDIM + d] = v;
            } else {
                Y[(size_t)m * DMODEL + n] = v;
            }
        }
    }
}

// ---------------------------------------------------------------------------
// Causal flash attention. Grid: (SEQ/128, BATCH*NHEADS), 128 threads.
// Each thread owns one q row; K/V tiles of 32x64 staged in smem.
// ---------------------------------------------------------------------------
__global__ __launch_bounds__(128)
void flash_kernel()
{
    __shared__ float Ks[32][64];
    __shared__ float Vs[32][64];

    const int tid = threadIdx.x;
    const int qb  = blockIdx.x;          // 0..15
    const int bh  = blockIdx.y;          // 0..63
    const int qglob = qb * 128 + tid;

    // Load my q row into registers (contiguous 64 floats in gmem)
    float q[HDIM];
    {
        const float4* qrow = (const float4*)(g_Q + ((size_t)bh * SEQ + qglob) * HDIM);
        #pragma unroll
        for (int k4 = 0; k4 < 16; k4++) ((float4*)q)[k4] = qrow[k4];
    }

    float o[HDIM];
    #pragma unroll
    for (int d = 0; d < HDIM; d++) o[d] = 0.f;
    float mrow = -INFINITY, lrow = 0.f;

    const float4* Kb = (const float4*)(g_K + (size_t)bh * SEQ * HDIM);
    const float4* Vb = (const float4*)(g_V + (size_t)bh * SEQ * HDIM);
    float4* kdst = (float4*)&Ks[0][0];
    float4* vdst = (float4*)&Vs[0][0];

    const int ktiles = (qb + 1) * 4;     // causal bound, 32 rows per tile
    const float scale = 0.125f;          // 1/sqrt(64)

    for (int kt = 0; kt < ktiles; kt++) {
        // stage K/V tile: 2048 floats = 512 float4 each, 128 threads
        const float4* ksrc = Kb + (size_t)kt * 512;
        const float4* vsrc = Vb + (size_t)kt * 512;
        #pragma unroll
        for (int i = 0; i < 4; i++) {
            kdst[tid + i * 128] = ksrc[tid + i * 128];
            vdst[tid + i * 128] = vsrc[tid + i * 128];
        }
        __syncthreads();

        const int kbase = kt * 32;
        float s[32];
        float mnew = mrow;
        #pragma unroll
        for (int j = 0; j < 32; j++) {
            const float4* krow = (const float4*)&Ks[j][0];
            float a = 0.f;
            #pragma unroll
            for (int k4 = 0; k4 < 16; k4++) {
                float4 kv = krow[k4];
                a = fmaf(q[k4 * 4 + 0], kv.x, a);
                a = fmaf(q[k4 * 4 + 1], kv.y, a);
                a = fmaf(q[k4 * 4 + 2], kv.z, a);
                a = fmaf(q[k4 * 4 + 3], kv.w, a);
            }
            a = (kbase + j <= qglob) ? a * scale : -INFINITY;
            s[j] = a;
            mnew = fmaxf(mnew, a);
        }

        const float corr = __expf(mrow - mnew);
        mrow = mnew;
        lrow *= corr;
        #pragma unroll
        for (int d = 0; d < HDIM; d++) o[d] *= corr;

        #pragma unroll
        for (int j = 0; j < 32; j++) {
            const float p = __expf(s[j] - mnew);
            lrow += p;
            const float4* vrow = (const float4*)&Vs[j][0];
            #pragma unroll
            for (int d4 = 0; d4 < 16; d4++) {
                float4 vv = vrow[d4];
                o[d4 * 4 + 0] = fmaf(p, vv.x, o[d4 * 4 + 0]);
                o[d4 * 4 + 1] = fmaf(p, vv.y, o[d4 * 4 + 1]);
                o[d4 * 4 + 2] = fmaf(p, vv.z, o[d4 * 4 + 2]);
                o[d4 * 4 + 3] = fmaf(p, vv.w, o[d4 * 4 + 3]);
            }
        }
        __syncthreads();
    }

    const float inv = 1.f / lrow;
    const int b = bh >> 4, h = bh & 15;
    float* out = g_A + ((size_t)(b * SEQ) + qglob) * DMODEL + h * HDIM;
    #pragma unroll
    for (int d4 = 0; d4 < 16; d4++) {
        float4 ov;
        ov.x = o[d4 * 4 + 0] * inv;
        ov.y = o[d4 * 4 + 1] * inv;
        ov.z = o[d4 * 4 + 2] * inv;
        ov.w = o[d4 * 4 + 3] * inv;
        ((float4*)out)[d4] = ov;
    }
}

// ---------------------------------------------------------------------------
extern "C" void kernel_launch(void* const* d_in, const int* in_sizes, int n_in,
                              void* d_out, int out_size)
{
    const float* x  = (const float*)d_in[0];
    // d_in[1] = mask (causal tril; applied analytically)
    const float* Wq = (const float*)d_in[2];
    const float* bq = (const float*)d_in[3];
    const float* Wk = (const float*)d_in[4];
    const float* bk = (const float*)d_in[5];
    const float* Wv = (const float*)d_in[6];
    const float* bv = (const float*)d_in[7];
    const float* Wo = (const float*)d_in[8];
    const float* bo = (const float*)d_in[9];
    float* out = (float*)d_out;

    float *Qp, *Kp, *Vp, *Ap;
    cudaGetSymbolAddress((void**)&Qp, g_Q);
    cudaGetSymbolAddress((void**)&Kp, g_K);
    cudaGetSymbolAddress((void**)&Vp, g_V);
    cudaGetSymbolAddress((void**)&Ap, g_A);

    dim3 ggrid(DMODEL / 128, MROWS / 128);   // (8, 64)
    gemm_kernel<1><<<ggrid, 256>>>(x, Wq, bq, Qp);
    gemm_kernel<1><<<ggrid, 256>>>(x, Wk, bk, Kp);
    gemm_kernel<1><<<ggrid, 256>>>(x, Wv, bv, Vp);

    dim3 fgrid(SEQ / 128, BATCH * NHEADS);   // (16, 64)
    flash_kernel<<<fgrid, 128>>>();

    gemm_kernel<0><<<ggrid, 256>>>(Ap, Wo, bo, out);
}

// round 7
// speedup vs baseline: 1.5192x; 1.5192x over previous
#include <cuda_runtime.h>
#include <math.h>
#include <stdint.h>

#define BATCH 4
#define SEQ   2048
#define DMODEL 1024
#define NHEADS 16
#define HDIM  64
#define MROWS (BATCH*SEQ)   // 8192

// Scratch (no cudaMalloc allowed)
__device__ float g_Q[BATCH*NHEADS*SEQ*HDIM];
__device__ float g_K[BATCH*NHEADS*SEQ*HDIM];
__device__ float g_V[BATCH*NHEADS*SEQ*HDIM];
__device__ float g_A[BATCH*SEQ*DMODEL];
__device__ float g_Wt[4u*1024u*1024u];   // 4 transposed weights [N,K]

__device__ __forceinline__ uint32_t f2tf(float x) {
    uint32_t u;
    asm("cvt.rna.tf32.f32 %0, %1;" : "=r"(u) : "f"(x));
    return u;
}

__device__ __forceinline__ void mma_tf32(float* c, const uint32_t* a, const uint32_t* b) {
    asm volatile(
        "mma.sync.aligned.m16n8k8.row.col.f32.tf32.tf32.f32 "
        "{%0,%1,%2,%3}, {%4,%5,%6,%7}, {%8,%9}, {%0,%1,%2,%3};"
        : "+f"(c[0]), "+f"(c[1]), "+f"(c[2]), "+f"(c[3])
        : "r"(a[0]), "r"(a[1]), "r"(a[2]), "r"(a[3]), "r"(b[0]), "r"(b[1]));
}

// ---------------------------------------------------------------------------
// Transpose: Wt[n,k] = W[k,n].  1024x1024. grid(32,32), block(32,8)
// ---------------------------------------------------------------------------
__global__ __launch_bounds__(256)
void transpose_kernel(const float* __restrict__ W, float* __restrict__ Wt)
{
    __shared__ float t[32][33];
    const int x0 = blockIdx.x * 32, y0 = blockIdx.y * 32;
    const int tx = threadIdx.x, ty = threadIdx.y;
    #pragma unroll
    for (int i = 0; i < 32; i += 8)
        t[ty + i][tx] = W[(size_t)(y0 + ty + i) * 1024 + x0 + tx];
    __syncthreads();
    #pragma unroll
    for (int i = 0; i < 32; i += 8)
        Wt[(size_t)(x0 + ty + i) * 1024 + y0 + tx] = t[tx][ty + i];
}

// ---------------------------------------------------------------------------
// Tensor-core GEMM via mma.sync tf32: Y = X @ W + bias, Bt = W^T ([N,K]).
// CTA 128x128x32, 256 threads = 8 warps (2x4), warp tile 64x32 (4x4 frags
// of m16n8k8), fp32 accum in registers. Smem stride 36 -> conflict-free
// fragment loads.
// ---------------------------------------------------------------------------
template<int OUT_HEADED>
__global__ __launch_bounds__(256)
void gemm_mma(const float* __restrict__ X, const float* __restrict__ Bt,
              const float* __restrict__ bias, float* __restrict__ Y)
{
    __shared__ float As[128][36];   // [m][k]
    __shared__ float Bs[128][36];   // [n][k]

    const int tid = threadIdx.x;
    const int wid = tid >> 5, lane = tid & 31;
    const int bn = blockIdx.x, bm = blockIdx.y;
    const int warp_m = wid >> 2, warp_n = wid & 3;
    const int g = lane >> 2, tig = lane & 3;
    const int m0 = warp_m * 64, n0 = warp_n * 32;

    float c[4][4][4];
    #pragma unroll
    for (int mf = 0; mf < 4; mf++)
        #pragma unroll
        for (int nf = 0; nf < 4; nf++)
            #pragma unroll
            for (int i = 0; i < 4; i++) c[mf][nf][i] = 0.f;

    const int lrow = tid >> 3;          // 0..31
    const int lc4  = (tid & 7) * 4;     // 0..28

    for (int k0 = 0; k0 < DMODEL; k0 += 32) {
        #pragma unroll
        for (int j = 0; j < 4; j++) {
            const int r = lrow + 32 * j;
            float4 av = *(const float4*)&X [(size_t)(bm * 128 + r) * DMODEL + k0 + lc4];
            float4 bv = *(const float4*)&Bt[(size_t)(bn * 128 + r) * DMODEL + k0 + lc4];
            As[r][lc4 + 0] = __uint_as_float(f2tf(av.x));
            As[r][lc4 + 1] = __uint_as_float(f2tf(av.y));
            As[r][lc4 + 2] = __uint_as_float(f2tf(av.z));
            As[r][lc4 + 3] = __uint_as_float(f2tf(av.w));
            Bs[r][lc4 + 0] = __uint_as_float(f2tf(bv.x));
            Bs[r][lc4 + 1] = __uint_as_float(f2tf(bv.y));
            Bs[r][lc4 + 2] = __uint_as_float(f2tf(bv.z));
            Bs[r][lc4 + 3] = __uint_as_float(f2tf(bv.w));
        }
        __syncthreads();

        #pragma unroll
        for (int kk = 0; kk < 32; kk += 8) {
            uint32_t a[4][4], b[4][2];
            #pragma unroll
            for (int mf = 0; mf < 4; mf++) {
                const int mr = m0 + mf * 16 + g;
                a[mf][0] = __float_as_uint(As[mr    ][kk + tig]);
                a[mf][1] = __float_as_uint(As[mr + 8][kk + tig]);
                a[mf][2] = __float_as_uint(As[mr    ][kk + tig + 4]);
                a[mf][3] = __float_as_uint(As[mr + 8][kk + tig + 4]);
            }
            #pragma unroll
            for (int nf = 0; nf < 4; nf++) {
                const int nr = n0 + nf * 8 + g;
                b[nf][0] = __float_as_uint(Bs[nr][kk + tig]);
                b[nf][1] = __float_as_uint(Bs[nr][kk + tig + 4]);
            }
            #pragma unroll
            for (int mf = 0; mf < 4; mf++)
                #pragma unroll
                for (int nf = 0; nf < 4; nf++)
                    mma_tf32(c[mf][nf], a[mf], b[nf]);
        }
        __syncthreads();
    }

    // Epilogue: c[mf][nf]: rows (g, g+8), cols (2*tig, 2*tig+1)
    #pragma unroll
    for (int mf = 0; mf < 4; mf++) {
        #pragma unroll
        for (int nf = 0; nf < 4; nf++) {
            const int col = bn * 128 + n0 + nf * 8 + 2 * tig;
            const float bz0 = bias[col], bz1 = bias[col + 1];
            #pragma unroll
            for (int half = 0; half < 2; half++) {
                const int m = bm * 128 + m0 + mf * 16 + g + half * 8;
                float2 v;
                v.x = c[mf][nf][half * 2 + 0] + bz0;
                v.y = c[mf][nf][half * 2 + 1] + bz1;
                if (OUT_HEADED) {
                    const int bb = m >> 11, t = m & 2047;
                    const int h = col >> 6, d = col & 63;
                    *(float2*)&Y[(((size_t)(bb * NHEADS + h) * SEQ) + t) * HDIM + d] = v;
                } else {
                    *(float2*)&Y[(size_t)m * DMODEL + col] = v;
                }
            }
        }
    }
}

// ---------------------------------------------------------------------------
// Causal flash attention (SIMT). Grid (16, 64), 128 threads.
// ---------------------------------------------------------------------------
__global__ __launch_bounds__(128)
void flash_kernel()
{
    __shared__ float Ks[32][64];
    __shared__ float Vs[32][64];

    const int tid = threadIdx.x;
    const int qb  = blockIdx.x;
    const int bh  = blockIdx.y;
    const int qglob = qb * 128 + tid;

    float q[HDIM];
    {
        const float4* qrow = (const float4*)(g_Q + ((size_t)bh * SEQ + qglob) * HDIM);
        #pragma unroll
        for (int k4 = 0; k4 < 16; k4++) ((float4*)q)[k4] = qrow[k4];
    }

    float o[HDIM];
    #pragma unroll
    for (int d = 0; d < HDIM; d++) o[d] = 0.f;
    float mrow = -INFINITY, lrow = 0.f;

    const float4* Kb = (const float4*)(g_K + (size_t)bh * SEQ * HDIM);
    const float4* Vb = (const float4*)(g_V + (size_t)bh * SEQ * HDIM);
    float4* kdst = (float4*)&Ks[0][0];
    float4* vdst = (float4*)&Vs[0][0];

    const int ktiles = (qb + 1) * 4;
    const float scale = 0.125f;

    for (int kt = 0; kt < ktiles; kt++) {
        const float4* ksrc = Kb + (size_t)kt * 512;
        const float4* vsrc = Vb + (size_t)kt * 512;
        #pragma unroll
        for (int i = 0; i < 4; i++) {
            kdst[tid + i * 128] = ksrc[tid + i * 128];
            vdst[tid + i * 128] = vsrc[tid + i * 128];
        }
        __syncthreads();

        const int kbase = kt * 32;
        float s[32];
        float mnew = mrow;
        #pragma unroll
        for (int j = 0; j < 32; j++) {
            const float4* krow = (const float4*)&Ks[j][0];
            float a = 0.f;
            #pragma unroll
            for (int k4 = 0; k4 < 16; k4++) {
                float4 kv = krow[k4];
                a = fmaf(q[k4 * 4 + 0], kv.x, a);
                a = fmaf(q[k4 * 4 + 1], kv.y, a);
                a = fmaf(q[k4 * 4 + 2], kv.z, a);
                a = fmaf(q[k4 * 4 + 3], kv.w, a);
            }
            a = (kbase + j <= qglob) ? a * scale : -INFINITY;
            s[j] = a;
            mnew = fmaxf(mnew, a);
        }

        const float corr = __expf(mrow - mnew);
        mrow = mnew;
        lrow *= corr;
        #pragma unroll
        for (int d = 0; d < HDIM; d++) o[d] *= corr;

        #pragma unroll
        for (int j = 0; j < 32; j++) {
            const float p = __expf(s[j] - mnew);
            lrow += p;
            const float4* vrow = (const float4*)&Vs[j][0];
            #pragma unroll
            for (int d4 = 0; d4 < 16; d4++) {
                float4 vv = vrow[d4];
                o[d4 * 4 + 0] = fmaf(p, vv.x, o[d4 * 4 + 0]);
                o[d4 * 4 + 1] = fmaf(p, vv.y, o[d4 * 4 + 1]);
                o[d4 * 4 + 2] = fmaf(p, vv.z, o[d4 * 4 + 2]);
                o[d4 * 4 + 3] = fmaf(p, vv.w, o[d4 * 4 + 3]);
            }
        }
        __syncthreads();
    }

    const float inv = 1.f / lrow;
    const int b = bh >> 4, h = bh & 15;
    float* out = g_A + ((size_t)(b * SEQ) + qglob) * DMODEL + h * HDIM;
    #pragma unroll
    for (int d4 = 0; d4 < 16; d4++) {
        float4 ov;
        ov.x = o[d4 * 4 + 0] * inv;
        ov.y = o[d4 * 4 + 1] * inv;
        ov.z = o[d4 * 4 + 2] * inv;
        ov.w = o[d4 * 4 + 3] * inv;
        ((float4*)out)[d4] = ov;
    }
}

// ---------------------------------------------------------------------------
extern "C" void kernel_launch(void* const* d_in, const int* in_sizes, int n_in,
                              void* d_out, int out_size)
{
    const float* x  = (const float*)d_in[0];
    const float* Wq = (const float*)d_in[2];
    const float* bq = (const float*)d_in[3];
    const float* Wk = (const float*)d_in[4];
    const float* bk = (const float*)d_in[5];
    const float* Wv = (const float*)d_in[6];
    const float* bv = (const float*)d_in[7];
    const float* Wo = (const float*)d_in[8];
    const float* bo = (const float*)d_in[9];
    float* out = (float*)d_out;

    float *Qp, *Kp, *Vp, *Ap, *Wt;
    cudaGetSymbolAddress((void**)&Qp, g_Q);
    cudaGetSymbolAddress((void**)&Kp, g_K);
    cudaGetSymbolAddress((void**)&Vp, g_V);
    cudaGetSymbolAddress((void**)&Ap, g_A);
    cudaGetSymbolAddress((void**)&Wt, g_Wt);

    dim3 tgrid(32, 32), tblk(32, 8);
    transpose_kernel<<<tgrid, tblk>>>(Wq, Wt + 0u * 1024u * 1024u);
    transpose_kernel<<<tgrid, tblk>>>(Wk, Wt + 1u * 1024u * 1024u);
    transpose_kernel<<<tgrid, tblk>>>(Wv, Wt + 2u * 1024u * 1024u);
    transpose_kernel<<<tgrid, tblk>>>(Wo, Wt + 3u * 1024u * 1024u);

    dim3 ggrid(DMODEL / 128, MROWS / 128);   // (8, 64)
    gemm_mma<1><<<ggrid, 256>>>(x, Wt + 0u * 1024u * 1024u, bq, Qp);
    gemm_mma<1><<<ggrid, 256>>>(x, Wt + 1u * 1024u * 1024u, bk, Kp);
    gemm_mma<1><<<ggrid, 256>>>(x, Wt + 2u * 1024u * 1024u, bv, Vp);

    dim3 fgrid(SEQ / 128, BATCH * NHEADS);
    flash_kernel<<<fgrid, 128>>>();

    gemm_mma<0><<<ggrid, 256>>>(Ap, Wt + 3u * 1024u * 1024u, bo, out);
}

// round 9
// speedup vs baseline: 3.8025x; 2.5030x over previous
#include <cuda_runtime.h>
#include <math.h>
#include <stdint.h>

#define BATCH 4
#define SEQ   2048
#define DMODEL 1024
#define NHEADS 16
#define HDIM  64
#define MROWS (BATCH*SEQ)   // 8192

// Scratch (no cudaMalloc allowed)
__device__ float g_Q[BATCH*NHEADS*SEQ*HDIM];
__device__ float g_K[BATCH*NHEADS*SEQ*HDIM];
__device__ float g_V[BATCH*NHEADS*SEQ*HDIM];
__device__ float g_A[BATCH*SEQ*DMODEL];
__device__ float g_Wt[4u*1024u*1024u];   // 4 transposed weights [N,K]

__device__ __forceinline__ uint32_t f2tf(float x) {
    uint32_t u;
    asm("cvt.rna.tf32.f32 %0, %1;" : "=r"(u) : "f"(x));
    return u;
}

__device__ __forceinline__ void mma_tf32(float* c, const uint32_t* a, const uint32_t* b) {
    asm volatile(
        "mma.sync.aligned.m16n8k8.row.col.f32.tf32.tf32.f32 "
        "{%0,%1,%2,%3}, {%4,%5,%6,%7}, {%8,%9}, {%0,%1,%2,%3};"
        : "+f"(c[0]), "+f"(c[1]), "+f"(c[2]), "+f"(c[3])
        : "r"(a[0]), "r"(a[1]), "r"(a[2]), "r"(a[3]), "r"(b[0]), "r"(b[1]));
}

// ---------------------------------------------------------------------------
// Transpose: Wt[n,k] = W[k,n].  1024x1024. grid(32,32), block(32,8)
// ---------------------------------------------------------------------------
__global__ __launch_bounds__(256)
void transpose_kernel(const float* __restrict__ W, float* __restrict__ Wt)
{
    __shared__ float t[32][33];
    const int x0 = blockIdx.x * 32, y0 = blockIdx.y * 32;
    const int tx = threadIdx.x, ty = threadIdx.y;
    #pragma unroll
    for (int i = 0; i < 32; i += 8)
        t[ty + i][tx] = W[(size_t)(y0 + ty + i) * 1024 + x0 + tx];
    __syncthreads();
    #pragma unroll
    for (int i = 0; i < 32; i += 8)
        Wt[(size_t)(x0 + ty + i) * 1024 + y0 + tx] = t[tx][ty + i];
}

// ---------------------------------------------------------------------------
// Tensor-core GEMM via mma.sync tf32: Y = X @ W + bias, Bt = W^T ([N,K]).
// ---------------------------------------------------------------------------
template<int OUT_HEADED>
__global__ __launch_bounds__(256)
void gemm_mma(const float* __restrict__ X, const float* __restrict__ Bt,
              const float* __restrict__ bias, float* __restrict__ Y)
{
    __shared__ float As[128][36];   // [m][k]
    __shared__ float Bs[128][36];   // [n][k]

    const int tid = threadIdx.x;
    const int wid = tid >> 5, lane = tid & 31;
    const int bn = blockIdx.x, bm = blockIdx.y;
    const int warp_m = wid >> 2, warp_n = wid & 3;
    const int g = lane >> 2, tig = lane & 3;
    const int m0 = warp_m * 64, n0 = warp_n * 32;

    float c[4][4][4];
    #pragma unroll
    for (int mf = 0; mf < 4; mf++)
        #pragma unroll
        for (int nf = 0; nf < 4; nf++)
            #pragma unroll
            for (int i = 0; i < 4; i++) c[mf][nf][i] = 0.f;

    const int lrow = tid >> 3;          // 0..31
    const int lc4  = (tid & 7) * 4;     // 0..28

    for (int k0 = 0; k0 < DMODEL; k0 += 32) {
        #pragma unroll
        for (int j = 0; j < 4; j++) {
            const int r = lrow + 32 * j;
            float4 av = *(const float4*)&X [(size_t)(bm * 128 + r) * DMODEL + k0 + lc4];
            float4 bv = *(const float4*)&Bt[(size_t)(bn * 128 + r) * DMODEL + k0 + lc4];
            As[r][lc4 + 0] = __uint_as_float(f2tf(av.x));
            As[r][lc4 + 1] = __uint_as_float(f2tf(av.y));
            As[r][lc4 + 2] = __uint_as_float(f2tf(av.z));
            As[r][lc4 + 3] = __uint_as_float(f2tf(av.w));
            Bs[r][lc4 + 0] = __uint_as_float(f2tf(bv.x));
            Bs[r][lc4 + 1] = __uint_as_float(f2tf(bv.y));
            Bs[r][lc4 + 2] = __uint_as_float(f2tf(bv.z));
            Bs[r][lc4 + 3] = __uint_as_float(f2tf(bv.w));
        }
        __syncthreads();

        #pragma unroll
        for (int kk = 0; kk < 32; kk += 8) {
            uint32_t a[4][4], b[4][2];
            #pragma unroll
            for (int mf = 0; mf < 4; mf++) {
                const int mr = m0 + mf * 16 + g;
                a[mf][0] = __float_as_uint(As[mr    ][kk + tig]);
                a[mf][1] = __float_as_uint(As[mr + 8][kk + tig]);
                a[mf][2] = __float_as_uint(As[mr    ][kk + tig + 4]);
                a[mf][3] = __float_as_uint(As[mr + 8][kk + tig + 4]);
            }
            #pragma unroll
            for (int nf = 0; nf < 4; nf++) {
                const int nr = n0 + nf * 8 + g;
                b[nf][0] = __float_as_uint(Bs[nr][kk + tig]);
                b[nf][1] = __float_as_uint(Bs[nr][kk + tig + 4]);
            }
            #pragma unroll
            for (int mf = 0; mf < 4; mf++)
                #pragma unroll
                for (int nf = 0; nf < 4; nf++)
                    mma_tf32(c[mf][nf], a[mf], b[nf]);
        }
        __syncthreads();
    }

    #pragma unroll
    for (int mf = 0; mf < 4; mf++) {
        #pragma unroll
        for (int nf = 0; nf < 4; nf++) {
            const int col = bn * 128 + n0 + nf * 8 + 2 * tig;
            const float bz0 = bias[col], bz1 = bias[col + 1];
            #pragma unroll
            for (int half = 0; half < 2; half++) {
                const int m = bm * 128 + m0 + mf * 16 + g + half * 8;
                float2 v;
                v.x = c[mf][nf][half * 2 + 0] + bz0;
                v.y = c[mf][nf][half * 2 + 1] + bz1;
                if (OUT_HEADED) {
                    const int bb = m >> 11, t = m & 2047;
                    const int h = col >> 6, d = col & 63;
                    *(float2*)&Y[(((size_t)(bb * NHEADS + h) * SEQ) + t) * HDIM + d] = v;
                } else {
                    *(float2*)&Y[(size_t)m * DMODEL + col] = v;
                }
            }
        }
    }
}

// ---------------------------------------------------------------------------
// Tensor-core causal flash attention (mma.sync tf32).
// Grid (16, 64), 256 threads = 8 warps; warp owns 16 q-rows.
// Q tile 128, KV tile 64. S = Q@K^T, online softmax in regs, O += P@V.
// Smem strides: 68 (== 4 mod 32) for Ps/Ks (rows indexed by g),
//               72 (== 8 mod 32) for Vs (rows indexed by tig). All fragment
//               accesses conflict-free.
// ---------------------------------------------------------------------------
#define PS_STRIDE 68
#define KS_STRIDE 68
#define VS_STRIDE 72
#define FLASH_SMEM ((128*PS_STRIDE + 64*KS_STRIDE + 64*VS_STRIDE) * 4)  // 70656 B

__global__ __launch_bounds__(256)
void flash_mma()
{
    extern __shared__ float sm[];
    float* Ps = sm;                          // [128][68] (Q staging, then P)
    float* Ks = sm + 128 * PS_STRIDE;        // [64][68]
    float* Vs = Ks + 64 * KS_STRIDE;         // [64][72]

    const int tid = threadIdx.x;
    const int wid = tid >> 5, lane = tid & 31;
    const int g = lane >> 2, tig = lane & 3;
    const int qb = blockIdx.x, bh = blockIdx.y;
    const int m0 = wid * 16;
    const int r0 = m0 + g, r1 = m0 + g + 8;
    const int qg0 = qb * 128 + r0, qg1 = qb * 128 + r1;

    // Stage Q tile into Ps (tf32-converted)
    {
        const float* Qb = g_Q + ((size_t)bh * SEQ + qb * 128) * HDIM;
        const int r = tid >> 1, c0 = (tid & 1) * 32;
        #pragma unroll
        for (int j = 0; j < 8; j++) {
            float4 v = *(const float4*)(Qb + (size_t)r * HDIM + c0 + j * 4);
            uint4 t = { f2tf(v.x), f2tf(v.y), f2tf(v.z), f2tf(v.w) };
            *(uint4*)(Ps + r * PS_STRIDE + c0 + j * 4) = t;
        }
    }
    __syncthreads();

    // Q fragments: register-resident for the whole kernel
    uint32_t qa[8][4];
    #pragma unroll
    for (int kf = 0; kf < 8; kf++) {
        qa[kf][0] = __float_as_uint(Ps[r0 * PS_STRIDE + kf * 8 + tig]);
        qa[kf][1] = __float_as_uint(Ps[r1 * PS_STRIDE + kf * 8 + tig]);
        qa[kf][2] = __float_as_uint(Ps[r0 * PS_STRIDE + kf * 8 + tig + 4]);
        qa[kf][3] = __float_as_uint(Ps[r1 * PS_STRIDE + kf * 8 + tig + 4]);
    }

    float o[8][4];
    #pragma unroll
    for (int nf = 0; nf < 8; nf++)
        #pragma unroll
        for (int i = 0; i < 4; i++) o[nf][i] = 0.f;
    float mr0 = -INFINITY, mr1 = -INFINITY, l0 = 0.f, l1 = 0.f;

    const int ktiles = (qb + 1) * 2;
    const float scale = 0.125f;   // 1/sqrt(64)

    for (int kt = 0; kt < ktiles; kt++) {
        __syncthreads();   // protect Ks/Vs (prev tile consumers done)
        {
            const float* Kt = g_K + ((size_t)bh * SEQ + kt * 64) * HDIM;
            const float* Vt = g_V + ((size_t)bh * SEQ + kt * 64) * HDIM;
            const int r = tid >> 2, c0 = (tid & 3) * 16;
            #pragma unroll
            for (int j = 0; j < 4; j++) {
                float4 kv = *(const float4*)(Kt + (size_t)r * HDIM + c0 + j * 4);
                float4 vv = *(const float4*)(Vt + (size_t)r * HDIM + c0 + j * 4);
                uint4 tk = { f2tf(kv.x), f2tf(kv.y), f2tf(kv.z), f2tf(kv.w) };
                uint4 tv = { f2tf(vv.x), f2tf(vv.y), f2tf(vv.z), f2tf(vv.w) };
                *(uint4*)(Ks + r * KS_STRIDE + c0 + j * 4) = tk;
                *(uint4*)(Vs + r * VS_STRIDE + c0 + j * 4) = tv;
            }
        }
        __syncthreads();

        // S = Q @ K^T  (warp tile 16x64: 8 n-frags, 8 k-steps)
        float s[8][4];
        #pragma unroll
        for (int nf = 0; nf < 8; nf++)
            #pragma unroll
            for (int i = 0; i < 4; i++) s[nf][i] = 0.f;

        #pragma unroll
        for (int kf = 0; kf < 8; kf++) {
            #pragma unroll
            for (int nf = 0; nf < 8; nf++) {
                uint32_t b[2];
                b[0] = __float_as_uint(Ks[(nf * 8 + g) * KS_STRIDE + kf * 8 + tig]);
                b[1] = __float_as_uint(Ks[(nf * 8 + g) * KS_STRIDE + kf * 8 + tig + 4]);
                mma_tf32(s[nf], qa[kf], b);
            }
        }

        // scale + causal mask (only diagonal tiles need the mask)
        const bool diag = (kt >= 2 * qb);
        #pragma unroll
        for (int nf = 0; nf < 8; nf++) {
            const int cb = kt * 64 + nf * 8 + 2 * tig;
            s[nf][0] *= scale; s[nf][1] *= scale;
            s[nf][2] *= scale; s[nf][3] *= scale;
            if (diag) {
                if (cb     > qg0) s[nf][0] = -INFINITY;
                if (cb + 1 > qg0) s[nf][1] = -INFINITY;
                if (cb     > qg1) s[nf][2] = -INFINITY;
                if (cb + 1 > qg1) s[nf][3] = -INFINITY;
            }
        }

        // row max (16 cols per thread + quad shuffle over tig lanes)
        float mn0 = s[0][0], mn1 = s[0][2];
        #pragma unroll
        for (int nf = 0; nf < 8; nf++) {
            mn0 = fmaxf(mn0, fmaxf(s[nf][0], s[nf][1]));
            mn1 = fmaxf(mn1, fmaxf(s[nf][2], s[nf][3]));
        }
        mn0 = fmaxf(mn0, __shfl_xor_sync(0xffffffffu, mn0, 1));
        mn0 = fmaxf(mn0, __shfl_xor_sync(0xffffffffu, mn0, 2));
        mn1 = fmaxf(mn1, __shfl_xor_sync(0xffffffffu, mn1, 1));
        mn1 = fmaxf(mn1, __shfl_xor_sync(0xffffffffu, mn1, 2));
        mn0 = fmaxf(mr0, mn0);
        mn1 = fmaxf(mr1, mn1);

        const float cr0 = __expf(mr0 - mn0);
        const float cr1 = __expf(mr1 - mn1);
        mr0 = mn0; mr1 = mn1;
        #pragma unroll
        for (int nf = 0; nf < 8; nf++) {
            o[nf][0] *= cr0; o[nf][1] *= cr0;
            o[nf][2] *= cr1; o[nf][3] *= cr1;
        }

        // P = exp(S - m); store tf32 P to smem; accumulate row sums
        float ps0 = 0.f, ps1 = 0.f;
        #pragma unroll
        for (int nf = 0; nf < 8; nf++) {
            const float p0 = __expf(s[nf][0] - mn0);
            const float p1 = __expf(s[nf][1] - mn0);
            const float p2 = __expf(s[nf][2] - mn1);
            const float p3 = __expf(s[nf][3] - mn1);
            ps0 += p0 + p1; ps1 += p2 + p3;
            uint2 u0 = { f2tf(p0), f2tf(p1) };
            uint2 u1 = { f2tf(p2), f2tf(p3) };
            *(uint2*)(Ps + r0 * PS_STRIDE + nf * 8 + 2 * tig) = u0;
            *(uint2*)(Ps + r1 * PS_STRIDE + nf * 8 + 2 * tig) = u1;
        }
        ps0 += __shfl_xor_sync(0xffffffffu, ps0, 1);
        ps0 += __shfl_xor_sync(0xffffffffu, ps0, 2);
        ps1 += __shfl_xor_sync(0xffffffffu, ps1, 1);
        ps1 += __shfl_xor_sync(0xffffffffu, ps1, 2);
        l0 = l0 * cr0 + ps0;
        l1 = l1 * cr1 + ps1;

        // O += P @ V  (P rows are warp-private -> no barrier needed)
        #pragma unroll
        for (int kf = 0; kf < 8; kf++) {
            uint32_t pa[4];
            pa[0] = __float_as_uint(Ps[r0 * PS_STRIDE + kf * 8 + tig]);
            pa[1] = __float_as_uint(Ps[r1 * PS_STRIDE + kf * 8 + tig]);
            pa[2] = __float_as_uint(Ps[r0 * PS_STRIDE + kf * 8 + tig + 4]);
            pa[3] = __float_as_uint(Ps[r1 * PS_STRIDE + kf * 8 + tig + 4]);
            #pragma unroll
            for (int nf = 0; nf < 8; nf++) {
                uint32_t b[2];
                b[0] = __float_as_uint(Vs[(kf * 8 + tig)     * VS_STRIDE + nf * 8 + g]);
                b[1] = __float_as_uint(Vs[(kf * 8 + tig + 4) * VS_STRIDE + nf * 8 + g]);
                mma_tf32(o[nf], pa, b);
            }
        }
    }

    // Epilogue: normalize and scatter into g_A [b, t, h*64+d]
    const float i0 = 1.f / l0, i1 = 1.f / l1;
    const int bb = bh >> 4, h = bh & 15;
    float* A0 = g_A + ((size_t)(bb * SEQ) + qg0) * DMODEL + h * HDIM;
    float* A1 = g_A + ((size_t)(bb * SEQ) + qg1) * DMODEL + h * HDIM;
    #pragma unroll
    for (int nf = 0; nf < 8; nf++) {
        float2 v0 = { o[nf][0] * i0, o[nf][1] * i0 };
        float2 v1 = { o[nf][2] * i1, o[nf][3] * i1 };
        *(float2*)(A0 + nf * 8 + 2 * tig) = v0;
        *(float2*)(A1 + nf * 8 + 2 * tig) = v1;
    }
}

// ---------------------------------------------------------------------------
extern "C" void kernel_launch(void* const* d_in, const int* in_sizes, int n_in,
                              void* d_out, int out_size)
{
    const float* x  = (const float*)d_in[0];
    const float* Wq = (const float*)d_in[2];
    const float* bq = (const float*)d_in[3];
    const float* Wk = (const float*)d_in[4];
    const float* bk = (const float*)d_in[5];
    const float* Wv = (const float*)d_in[6];
    const float* bv = (const float*)d_in[7];
    const float* Wo = (const float*)d_in[8];
    const float* bo = (const float*)d_in[9];
    float* out = (float*)d_out;

    float *Qp, *Kp, *Vp, *Ap, *Wt;
    cudaGetSymbolAddress((void**)&Qp, g_Q);
    cudaGetSymbolAddress((void**)&Kp, g_K);
    cudaGetSymbolAddress((void**)&Vp, g_V);
    cudaGetSymbolAddress((void**)&Ap, g_A);
    cudaGetSymbolAddress((void**)&Wt, g_Wt);

    cudaFuncSetAttribute(flash_mma, cudaFuncAttributeMaxDynamicSharedMemorySize,
                         FLASH_SMEM);

    dim3 tgrid(32, 32), tblk(32, 8);
    transpose_kernel<<<tgrid, tblk>>>(Wq, Wt + 0u * 1024u * 1024u);
    transpose_kernel<<<tgrid, tblk>>>(Wk, Wt + 1u * 1024u * 1024u);
    transpose_kernel<<<tgrid, tblk>>>(Wv, Wt + 2u * 1024u * 1024u);
    transpose_kernel<<<tgrid, tblk>>>(Wo, Wt + 3u * 1024u * 1024u);

    dim3 ggrid(DMODEL / 128, MROWS / 128);   // (8, 64)
    gemm_mma<1><<<ggrid, 256>>>(x, Wt + 0u * 1024u * 1024u, bq, Qp);
    gemm_mma<1><<<ggrid, 256>>>(x, Wt + 1u * 1024u * 1024u, bk, Kp);
    gemm_mma<1><<<ggrid, 256>>>(x, Wt + 2u * 1024u * 1024u, bv, Vp);

    dim3 fgrid(SEQ / 128, BATCH * NHEADS);   // (16, 64)
    flash_mma<<<fgrid, 256, FLASH_SMEM>>>();

    gemm_mma<0><<<ggrid, 256>>>(Ap, Wt + 3u * 1024u * 1024u, bo, out);
}

// round 10
// speedup vs baseline: 4.1894x; 1.1017x over previous
#include <cuda_runtime.h>
#include <math.h>
#include <stdint.h>

#define BATCH 4
#define SEQ   2048
#define DMODEL 1024
#define NHEADS 16
#define HDIM  64
#define MROWS (BATCH*SEQ)   // 8192

// Scratch (no cudaMalloc allowed)
__device__ float g_Q[BATCH*NHEADS*SEQ*HDIM];
__device__ float g_K[BATCH*NHEADS*SEQ*HDIM];
__device__ float g_V[BATCH*NHEADS*SEQ*HDIM];
__device__ float g_A[BATCH*SEQ*DMODEL];
__device__ float g_Xr[(size_t)MROWS*DMODEL];   // tf32-rounded x
__device__ float g_Wt[4u*1024u*1024u];         // 4 transposed+rounded weights [N,K]

__device__ __forceinline__ uint32_t f2tf(float x) {
    uint32_t u;
    asm("cvt.rna.tf32.f32 %0, %1;" : "=r"(u) : "f"(x));
    return u;
}
__device__ __forceinline__ uint32_t smem_u32(const void* p) {
    uint32_t a;
    asm("{ .reg .u64 t; cvta.to.shared.u64 t, %1; cvt.u32.u64 %0, t; }"
        : "=r"(a) : "l"(p));
    return a;
}
__device__ __forceinline__ void mma_tf32(float* c, const uint32_t* a, const uint32_t* b) {
    asm volatile(
        "mma.sync.aligned.m16n8k8.row.col.f32.tf32.tf32.f32 "
        "{%0,%1,%2,%3}, {%4,%5,%6,%7}, {%8,%9}, {%0,%1,%2,%3};"
        : "+f"(c[0]), "+f"(c[1]), "+f"(c[2]), "+f"(c[3])
        : "r"(a[0]), "r"(a[1]), "r"(a[2]), "r"(a[3]), "r"(b[0]), "r"(b[1]));
}
#define CP_ASYNC16(dst, src) \
    asm volatile("cp.async.cg.shared.global [%0], [%1], 16;" :: "r"(dst), "l"(src))
#define CP_COMMIT() asm volatile("cp.async.commit_group;" ::: "memory")
#define CP_WAIT1()  asm volatile("cp.async.wait_group 1;"  ::: "memory")
#define CP_WAIT0()  asm volatile("cp.async.wait_group 0;"  ::: "memory")

// ---------------------------------------------------------------------------
// Round x to tf32 (RNA) once. 2.1M float4s.
// ---------------------------------------------------------------------------
__global__ __launch_bounds__(256)
void round_kernel(const float4* __restrict__ in, float4* __restrict__ out)
{
    const int i = blockIdx.x * 256 + threadIdx.x;
    float4 v = in[i];
    uint4 t = { f2tf(v.x), f2tf(v.y), f2tf(v.z), f2tf(v.w) };
    out[i] = *(float4*)&t;
}

// ---------------------------------------------------------------------------
// Transpose + round: Wt[n,k] = tf32(W[k,n]). 1024x1024. grid(32,32), blk(32,8)
// ---------------------------------------------------------------------------
__global__ __launch_bounds__(256)
void transpose_kernel(const float* __restrict__ W, float* __restrict__ Wt)
{
    __shared__ float t[32][33];
    const int x0 = blockIdx.x * 32, y0 = blockIdx.y * 32;
    const int tx = threadIdx.x, ty = threadIdx.y;
    #pragma unroll
    for (int i = 0; i < 32; i += 8)
        t[ty + i][tx] = W[(size_t)(y0 + ty + i) * 1024 + x0 + tx];
    __syncthreads();
    #pragma unroll
    for (int i = 0; i < 32; i += 8)
        Wt[(size_t)(x0 + ty + i) * 1024 + y0 + tx] =
            __uint_as_float(f2tf(t[tx][ty + i]));
}

// ---------------------------------------------------------------------------
// Pipelined tensor-core GEMM (cp.async 2-stage): Y = X @ W + bias.
// Inputs X, Bt MUST be pre-rounded to tf32. blockIdx.z selects weight slice
// z from WtBase, bias/output from the pointer triples.
// CTA 128x128x32, 256 thr, warp 64x32 of m16n8k8. Smem stride 36 (=4 mod 32)
// -> conflict-free fragment LDS. 2 stages x (As+Bs) = 73.7 KB, 2 CTA/SM.
// ---------------------------------------------------------------------------
#define GST (128*36)                 // floats per tile per stage
#define GP_SMEM (4*GST*4)            // 73728 B: As[2]+Bs[2]

template<int OUT_HEADED>
__global__ __launch_bounds__(256, 2)
void gemm_pipe(const float* __restrict__ X, const float* __restrict__ WtBase,
               const float* b0, const float* b1, const float* b2,
               float* y0, float* y1, float* y2)
{
    extern __shared__ float sm[];
    float* As = sm;            // [2][128][36]
    float* Bs = sm + 2 * GST;  // [2][128][36]

    const int z = blockIdx.z;
    const float* Bt   = WtBase + (size_t)z * 1024u * 1024u;
    const float* bias = (z == 0) ? b0 : (z == 1) ? b1 : b2;
    float*       Y    = (z == 0) ? y0 : (z == 1) ? y1 : y2;

    const int tid = threadIdx.x;
    const int wid = tid >> 5, lane = tid & 31;
    const int bn = blockIdx.x, bm = blockIdx.y;
    const int warp_m = wid >> 2, warp_n = wid & 3;
    const int g = lane >> 2, tig = lane & 3;
    const int m0 = warp_m * 64, n0 = warp_n * 32;

    const float* Xb  = X  + (size_t)(bm * 128) * DMODEL;
    const float* Btb = Bt + (size_t)(bn * 128) * DMODEL;

    // cp.async staging map: 4 x (A chunk + B chunk) per thread per k-chunk
    const int ldr[4] = { (tid + 0) >> 3, (tid + 256) >> 3,
                         (tid + 512) >> 3, (tid + 768) >> 3 };
    const int ldc = (tid & 7) * 4;

    #define ISSUE(stage, chunk) do { \
        const int _k0 = (chunk) * 32; \
        _Pragma("unroll") \
        for (int _j = 0; _j < 4; _j++) { \
            const int _r = ldr[_j]; \
            CP_ASYNC16(smem_u32(As + (stage) * GST + _r * 36 + ldc), \
                       Xb  + (size_t)_r * DMODEL + _k0 + ldc); \
            CP_ASYNC16(smem_u32(Bs + (stage) * GST + _r * 36 + ldc), \
                       Btb + (size_t)_r * DMODEL + _k0 + ldc); \
        } \
        CP_COMMIT(); \
    } while (0)

    float c[4][4][4];
    #pragma unroll
    for (int mf = 0; mf < 4; mf++)
        #pragma unroll
        for (int nf = 0; nf < 4; nf++)
            #pragma unroll
            for (int i = 0; i < 4; i++) c[mf][nf][i] = 0.f;

    ISSUE(0, 0);
    ISSUE(1, 1);

    for (int ch = 0; ch < 32; ch++) {
        const int s = ch & 1;
        if (ch + 2 < 32) { CP_WAIT1(); } else { CP_WAIT0(); }
        __syncthreads();

        const float* A0 = As + s * GST;
        const float* B0 = Bs + s * GST;
        #pragma unroll
        for (int kk = 0; kk < 32; kk += 8) {
            uint32_t a[4][4], b[4][2];
            #pragma unroll
            for (int mf = 0; mf < 4; mf++) {
                const int mr = m0 + mf * 16 + g;
                a[mf][0] = __float_as_uint(A0[(mr    ) * 36 + kk + tig]);
                a[mf][1] = __float_as_uint(A0[(mr + 8) * 36 + kk + tig]);
                a[mf][2] = __float_as_uint(A0[(mr    ) * 36 + kk + tig + 4]);
                a[mf][3] = __float_as_uint(A0[(mr + 8) * 36 + kk + tig + 4]);
            }
            #pragma unroll
            for (int nf = 0; nf < 4; nf++) {
                const int nr = n0 + nf * 8 + g;
                b[nf][0] = __float_as_uint(B0[nr * 36 + kk + tig]);
                b[nf][1] = __float_as_uint(B0[nr * 36 + kk + tig + 4]);
            }
            #pragma unroll
            for (int mf = 0; mf < 4; mf++)
                #pragma unroll
                for (int nf = 0; nf < 4; nf++)
                    mma_tf32(c[mf][nf], a[mf], b[nf]);
        }
        __syncthreads();
        if (ch + 2 < 32) ISSUE(s, ch + 2);
    }

    // Epilogue. OUT_HEADED: scatter to [b,h,t,d], tf32-rounded (feeds flash).
    #pragma unroll
    for (int mf = 0; mf < 4; mf++) {
        #pragma unroll
        for (int nf = 0; nf < 4; nf++) {
            const int col = bn * 128 + n0 + nf * 8 + 2 * tig;
            const float bz0 = bias[col], bz1 = bias[col + 1];
            #pragma unroll
            for (int half = 0; half < 2; half++) {
                const int m = bm * 128 + m0 + mf * 16 + g + half * 8;
                float2 v;
                v.x = c[mf][nf][half * 2 + 0] + bz0;
                v.y = c[mf][nf][half * 2 + 1] + bz1;
                if (OUT_HEADED) {
                    v.x = __uint_as_float(f2tf(v.x));
                    v.y = __uint_as_float(f2tf(v.y));
                    const int bb = m >> 11, t = m & 2047;
                    const int h = col >> 6, d = col & 63;
                    *(float2*)&Y[(((size_t)(bb * NHEADS + h) * SEQ) + t) * HDIM + d] = v;
                } else {
                    *(float2*)&Y[(size_t)m * DMODEL + col] = v;
                }
            }
        }
    }
    #undef ISSUE
}

// ---------------------------------------------------------------------------
// Tensor-core causal flash attention (mma.sync tf32). Q/K/V pre-rounded.
// Grid (16, 64), 256 threads = 8 warps; warp owns 16 q-rows.
// ---------------------------------------------------------------------------
#define PS_STRIDE 68
#define KS_STRIDE 68
#define VS_STRIDE 72
#define FLASH_SMEM ((128*PS_STRIDE + 64*KS_STRIDE + 64*VS_STRIDE) * 4)  // 70656 B

__global__ __launch_bounds__(256)
void flash_mma()
{
    extern __shared__ float sm[];
    float* Ps = sm;                          // [128][68] (Q staging, then P)
    float* Ks = sm + 128 * PS_STRIDE;        // [64][68]
    float* Vs = Ks + 64 * KS_STRIDE;         // [64][72]

    const int tid = threadIdx.x;
    const int wid = tid >> 5, lane = tid & 31;
    const int g = lane >> 2, tig = lane & 3;
    const int qb = blockIdx.x, bh = blockIdx.y;
    const int m0 = wid * 16;
    const int r0 = m0 + g, r1 = m0 + g + 8;
    const int qg0 = qb * 128 + r0, qg1 = qb * 128 + r1;

    // Stage Q tile (already tf32-rounded)
    {
        const float* Qb = g_Q + ((size_t)bh * SEQ + qb * 128) * HDIM;
        const int r = tid >> 1, c0 = (tid & 1) * 32;
        #pragma unroll
        for (int j = 0; j < 8; j++)
            *(float4*)(Ps + r * PS_STRIDE + c0 + j * 4) =
                *(const float4*)(Qb + (size_t)r * HDIM + c0 + j * 4);
    }
    __syncthreads();

    uint32_t qa[8][4];
    #pragma unroll
    for (int kf = 0; kf < 8; kf++) {
        qa[kf][0] = __float_as_uint(Ps[r0 * PS_STRIDE + kf * 8 + tig]);
        qa[kf][1] = __float_as_uint(Ps[r1 * PS_STRIDE + kf * 8 + tig]);
        qa[kf][2] = __float_as_uint(Ps[r0 * PS_STRIDE + kf * 8 + tig + 4]);
        qa[kf][3] = __float_as_uint(Ps[r1 * PS_STRIDE + kf * 8 + tig + 4]);
    }

    float o[8][4];
    #pragma unroll
    for (int nf = 0; nf < 8; nf++)
        #pragma unroll
        for (int i = 0; i < 4; i++) o[nf][i] = 0.f;
    float mr0 = -INFINITY, mr1 = -INFINITY, l0 = 0.f, l1 = 0.f;

    const int ktiles = (qb + 1) * 2;
    const float scale = 0.125f;   // 1/sqrt(64)

    for (int kt = 0; kt < ktiles; kt++) {
        __syncthreads();
        {
            const float* Kt = g_K + ((size_t)bh * SEQ + kt * 64) * HDIM;
            const float* Vt = g_V + ((size_t)bh * SEQ + kt * 64) * HDIM;
            const int r = tid >> 2, c0 = (tid & 3) * 16;
            #pragma unroll
            for (int j = 0; j < 4; j++) {
                *(float4*)(Ks + r * KS_STRIDE + c0 + j * 4) =
                    *(const float4*)(Kt + (size_t)r * HDIM + c0 + j * 4);
                *(float4*)(Vs + r * VS_STRIDE + c0 + j * 4) =
                    *(const float4*)(Vt + (size_t)r * HDIM + c0 + j * 4);
            }
        }
        __syncthreads();

        float s[8][4];
        #pragma unroll
        for (int nf = 0; nf < 8; nf++)
            #pragma unroll
            for (int i = 0; i < 4; i++) s[nf][i] = 0.f;

        #pragma unroll
        for (int kf = 0; kf < 8; kf++) {
            #pragma unroll
            for (int nf = 0; nf < 8; nf++) {
                uint32_t b[2];
                b[0] = __float_as_uint(Ks[(nf * 8 + g) * KS_STRIDE + kf * 8 + tig]);
                b[1] = __float_as_uint(Ks[(nf * 8 + g) * KS_STRIDE + kf * 8 + tig + 4]);
                mma_tf32(s[nf], qa[kf], b);
            }
        }

        const bool diag = (kt >= 2 * qb);
        #pragma unroll
        for (int nf = 0; nf < 8; nf++) {
            const int cb = kt * 64 + nf * 8 + 2 * tig;
            s[nf][0] *= scale; s[nf][1] *= scale;
            s[nf][2] *= scale; s[nf][3] *= scale;
            if (diag) {
                if (cb     > qg0) s[nf][0] = -INFINITY;
                if (cb + 1 > qg0) s[nf][1] = -INFINITY;
                if (cb     > qg1) s[nf][2] = -INFINITY;
                if (cb + 1 > qg1) s[nf][3] = -INFINITY;
            }
        }

        float mn0 = s[0][0], mn1 = s[0][2];
        #pragma unroll
        for (int nf = 0; nf < 8; nf++) {
            mn0 = fmaxf(mn0, fmaxf(s[nf][0], s[nf][1]));
            mn1 = fmaxf(mn1, fmaxf(s[nf][2], s[nf][3]));
        }
        mn0 = fmaxf(mn0, __shfl_xor_sync(0xffffffffu, mn0, 1));
        mn0 = fmaxf(mn0, __shfl_xor_sync(0xffffffffu, mn0, 2));
        mn1 = fmaxf(mn1, __shfl_xor_sync(0xffffffffu, mn1, 1));
        mn1 = fmaxf(mn1, __shfl_xor_sync(0xffffffffu, mn1, 2));
        mn0 = fmaxf(mr0, mn0);
        mn1 = fmaxf(mr1, mn1);

        const float cr0 = __expf(mr0 - mn0);
        const float cr1 = __expf(mr1 - mn1);
        mr0 = mn0; mr1 = mn1;
        #pragma unroll
        for (int nf = 0; nf < 8; nf++) {
            o[nf][0] *= cr0; o[nf][1] *= cr0;
            o[nf][2] *= cr1; o[nf][3] *= cr1;
        }

        float ps0 = 0.f, ps1 = 0.f;
        #pragma unroll
        for (int nf = 0; nf < 8; nf++) {
            const float p0 = __expf(s[nf][0] - mn0);
            const float p1 = __expf(s[nf][1] - mn0);
            const float p2 = __expf(s[nf][2] - mn1);
            const float p3 = __expf(s[nf][3] - mn1);
            ps0 += p0 + p1; ps1 += p2 + p3;
            uint2 u0 = { f2tf(p0), f2tf(p1) };
            uint2 u1 = { f2tf(p2), f2tf(p3) };
            *(uint2*)(Ps + r0 * PS_STRIDE + nf * 8 + 2 * tig) = u0;
            *(uint2*)(Ps + r1 * PS_STRIDE + nf * 8 + 2 * tig) = u1;
        }
        ps0 += __shfl_xor_sync(0xffffffffu, ps0, 1);
        ps0 += __shfl_xor_sync(0xffffffffu, ps0, 2);
        ps1 += __shfl_xor_sync(0xffffffffu, ps1, 1);
        ps1 += __shfl_xor_sync(0xffffffffu, ps1, 2);
        l0 = l0 * cr0 + ps0;
        l1 = l1 * cr1 + ps1;

        #pragma unroll
        for (int kf = 0; kf < 8; kf++) {
            uint32_t pa[4];
            pa[0] = __float_as_uint(Ps[r0 * PS_STRIDE + kf * 8 + tig]);
            pa[1] = __float_as_uint(Ps[r1 * PS_STRIDE + kf * 8 + tig]);
            pa[2] = __float_as_uint(Ps[r0 * PS_STRIDE + kf * 8 + tig + 4]);
            pa[3] = __float_as_uint(Ps[r1 * PS_STRIDE + kf * 8 + tig + 4]);
            #pragma unroll
            for (int nf = 0; nf < 8; nf++) {
                uint32_t b[2];
                b[0] = __float_as_uint(Vs[(kf * 8 + tig)     * VS_STRIDE + nf * 8 + g]);
                b[1] = __float_as_uint(Vs[(kf * 8 + tig + 4) * VS_STRIDE + nf * 8 + g]);
                mma_tf32(o[nf], pa, b);
            }
        }
    }

    // Epilogue: normalize, round to tf32 (feeds final GEMM A operand)
    const float i0 = 1.f / l0, i1 = 1.f / l1;
    const int bb = bh >> 4, h = bh & 15;
    float* A0 = g_A + ((size_t)(bb * SEQ) + qg0) * DMODEL + h * HDIM;
    float* A1 = g_A + ((size_t)(bb * SEQ) + qg1) * DMODEL + h * HDIM;
    #pragma unroll
    for (int nf = 0; nf < 8; nf++) {
        uint2 v0 = { f2tf(o[nf][0] * i0), f2tf(o[nf][1] * i0) };
        uint2 v1 = { f2tf(o[nf][2] * i1), f2tf(o[nf][3] * i1) };
        *(uint2*)(A0 + nf * 8 + 2 * tig) = v0;
        *(uint2*)(A1 + nf * 8 + 2 * tig) = v1;
    }
}

// ---------------------------------------------------------------------------
extern "C" void kernel_launch(void* const* d_in, const int* in_sizes, int n_in,
                              void* d_out, int out_size)
{
    const float* x  = (const float*)d_in[0];
    const float* Wq = (const float*)d_in[2];
    const float* bq = (const float*)d_in[3];
    const float* Wk = (const float*)d_in[4];
    const float* bk = (const float*)d_in[5];
    const float* Wv = (const float*)d_in[6];
    const float* bv = (const float*)d_in[7];
    const float* Wo = (const float*)d_in[8];
    const float* bo = (const float*)d_in[9];
    float* out = (float*)d_out;

    float *Qp, *Kp, *Vp, *Ap, *Wt, *Xr;
    cudaGetSymbolAddress((void**)&Qp, g_Q);
    cudaGetSymbolAddress((void**)&Kp, g_K);
    cudaGetSymbolAddress((void**)&Vp, g_V);
    cudaGetSymbolAddress((void**)&Ap, g_A);
    cudaGetSymbolAddress((void**)&Wt, g_Wt);
    cudaGetSymbolAddress((void**)&Xr, g_Xr);

    cudaFuncSetAttribute(flash_mma, cudaFuncAttributeMaxDynamicSharedMemorySize,
                         FLASH_SMEM);
    cudaFuncSetAttribute(gemm_pipe<1>, cudaFuncAttributeMaxDynamicSharedMemorySize,
                         GP_SMEM);
    cudaFuncSetAttribute(gemm_pipe<0>, cudaFuncAttributeMaxDynamicSharedMemorySize,
                         GP_SMEM);

    // Pre-round x; transpose+round weights
    round_kernel<<<(MROWS * DMODEL) / (256 * 4), 256>>>((const float4*)x, (float4*)Xr);
    dim3 tgrid(32, 32), tblk(32, 8);
    transpose_kernel<<<tgrid, tblk>>>(Wq, Wt + 0u * 1024u * 1024u);
    transpose_kernel<<<tgrid, tblk>>>(Wk, Wt + 1u * 1024u * 1024u);
    transpose_kernel<<<tgrid, tblk>>>(Wv, Wt + 2u * 1024u * 1024u);
    transpose_kernel<<<tgrid, tblk>>>(Wo, Wt + 3u * 1024u * 1024u);

    // Fused QKV projection (z selects head)
    dim3 qkvgrid(DMODEL / 128, MROWS / 128, 3);   // (8, 64, 3)
    gemm_pipe<1><<<qkvgrid, 256, GP_SMEM>>>(Xr, Wt, bq, bk, bv, Qp, Kp, Vp);

    dim3 fgrid(SEQ / 128, BATCH * NHEADS);        // (16, 64)
    flash_mma<<<fgrid, 256, FLASH_SMEM>>>();

    dim3 ogrid(DMODEL / 128, MROWS / 128, 1);
    gemm_pipe<0><<<ogrid, 256, GP_SMEM>>>(Ap, Wt + 3u * 1024u * 1024u,
                                          bo, bo, bo, out, out, out);
}

// round 13
// speedup vs baseline: 7.1378x; 1.7038x over previous
#include <cuda_runtime.h>
#include <cuda_fp16.h>
#include <math.h>
#include <stdint.h>

#define BATCH 4
#define SEQ   2048
#define DMODEL 1024
#define NHEADS 16
#define HDIM  64
#define MROWS (BATCH*SEQ)   // 8192

// Scratch (no cudaMalloc allowed) — all fp16
__device__ __half g_Qh[(size_t)BATCH*NHEADS*SEQ*HDIM];
__device__ __half g_Kh[(size_t)BATCH*NHEADS*SEQ*HDIM];
__device__ __half g_Vh[(size_t)BATCH*NHEADS*SEQ*HDIM];
__device__ __half g_Ah[(size_t)BATCH*SEQ*DMODEL];
__device__ __half g_Xh[(size_t)MROWS*DMODEL];
__device__ __half g_Wth[4u*1024u*1024u];     // 4 transposed weights [N,K] fp16

__device__ __forceinline__ uint32_t smem_u32(const void* p) {
    uint32_t a;
    asm("{ .reg .u64 t; cvta.to.shared.u64 t, %1; cvt.u32.u64 %0, t; }"
        : "=r"(a) : "l"(p));
    return a;
}
__device__ __forceinline__ void mma_f16(float* c, const uint32_t* a, const uint32_t* b) {
    asm volatile(
        "mma.sync.aligned.m16n8k16.row.col.f32.f16.f16.f32 "
        "{%0,%1,%2,%3}, {%4,%5,%6,%7}, {%8,%9}, {%0,%1,%2,%3};"
        : "+f"(c[0]), "+f"(c[1]), "+f"(c[2]), "+f"(c[3])
        : "r"(a[0]), "r"(a[1]), "r"(a[2]), "r"(a[3]), "r"(b[0]), "r"(b[1]));
}
__device__ __forceinline__ uint32_t pack_h2(float x, float y) {
    __half2 h = __floats2half2_rn(x, y);
    return *(uint32_t*)&h;
}
#define CP_ASYNC16(dst, src) \
    asm volatile("cp.async.cg.shared.global [%0], [%1], 16;" :: "r"(dst), "l"(src))
#define CP_COMMIT() asm volatile("cp.async.commit_group;" ::: "memory")
#define CP_WAIT1()  asm volatile("cp.async.wait_group 1;"  ::: "memory")
#define CP_WAIT0()  asm volatile("cp.async.wait_group 0;"  ::: "memory")

// ---------------------------------------------------------------------------
// Convert x to fp16. 8 floats -> 8 halves per thread.
// ---------------------------------------------------------------------------
__global__ __launch_bounds__(256)
void tohalf_kernel(const float4* __restrict__ in, uint4* __restrict__ out)
{
    const int i = blockIdx.x * 256 + threadIdx.x;
    float4 v0 = in[2 * i], v1 = in[2 * i + 1];
    uint4 o;
    o.x = pack_h2(v0.x, v0.y); o.y = pack_h2(v0.z, v0.w);
    o.z = pack_h2(v1.x, v1.y); o.w = pack_h2(v1.z, v1.w);
    out[i] = o;
}

// ---------------------------------------------------------------------------
// Transpose + halve: Wt[n,k] = fp16(W[k,n]). grid(32,32), blk(32,8)
// ---------------------------------------------------------------------------
__global__ __launch_bounds__(256)
void transpose_kernel(const float* __restrict__ W, __half* __restrict__ Wt)
{
    __shared__ float t[32][33];
    const int x0 = blockIdx.x * 32, y0 = blockIdx.y * 32;
    const int tx = threadIdx.x, ty = threadIdx.y;
    #pragma unroll
    for (int i = 0; i < 32; i += 8)
        t[ty + i][tx] = W[(size_t)(y0 + ty + i) * 1024 + x0 + tx];
    __syncthreads();
    #pragma unroll
    for (int i = 0; i < 32; i += 8)
        Wt[(size_t)(x0 + ty + i) * 1024 + y0 + tx] = __float2half_rn(t[tx][ty + i]);
}

// ---------------------------------------------------------------------------
// Pipelined fp16 tensor-core GEMM (cp.async 2-stage): Y = X @ W + bias.
// CTA 128x128x32, 256 thr, warp 64x32 of m16n8k16 (2 k-steps/chunk).
// Smem half tiles stride 40 (word ≡ 20·g+tig mod 32, conflict-free).
// OUT_HEADED=1: write half to [b,h,t,d]; 0: write float +bias to [m,n].
// ---------------------------------------------------------------------------
#define GSTH (128*40)                 // halves per tile per stage
#define GP_SMEM (4*GSTH*2)            // 40960 B

template<int OUT_HEADED>
__global__ __launch_bounds__(256, 2)
void gemm_pipe(const __half* __restrict__ X, const __half* __restrict__ WtBase,
               const float* b0, const float* b1, const float* b2,
               void* y0, void* y1, void* y2)
{
    extern __shared__ __half smh[];
    __half* As = smh;              // [2][128][40]
    __half* Bs = smh + 2 * GSTH;   // [2][128][40]

    const int z = blockIdx.z;
    const __half* Bt   = WtBase + (size_t)z * 1024u * 1024u;
    const float*  bias = (z == 0) ? b0 : (z == 1) ? b1 : b2;
    void*         Yv   = (z == 0) ? y0 : (z == 1) ? y1 : y2;

    const int tid = threadIdx.x;
    const int wid = tid >> 5, lane = tid & 31;
    const int bn = blockIdx.x, bm = blockIdx.y;
    const int warp_m = wid >> 2, warp_n = wid & 3;
    const int g = lane >> 2, tig = lane & 3;
    const int m0 = warp_m * 64, n0 = warp_n * 32;

    const __half* Xb  = X  + (size_t)(bm * 128) * DMODEL;
    const __half* Btb = Bt + (size_t)(bn * 128) * DMODEL;

    // staging: A/B tiles 128 rows x 32 halves (64B = 4 x 16B chunks).
    // 512 chunks per tile; thread does chunks {tid, tid+256} for A and B.
    #define ISSUE(stage, chunk) do { \
        const int _k0 = (chunk) * 32; \
        _Pragma("unroll") \
        for (int _j = 0; _j < 2; _j++) { \
            const int _c = tid + _j * 256; \
            const int _r = _c >> 2, _o = (_c & 3) * 8; \
            CP_ASYNC16(smem_u32(As + (stage) * GSTH + _r * 40 + _o), \
                       Xb  + (size_t)_r * DMODEL + _k0 + _o); \
            CP_ASYNC16(smem_u32(Bs + (stage) * GSTH + _r * 40 + _o), \
                       Btb + (size_t)_r * DMODEL + _k0 + _o); \
        } \
        CP_COMMIT(); \
    } while (0)

    float c[4][4][4];
    #pragma unroll
    for (int mf = 0; mf < 4; mf++)
        #pragma unroll
        for (int nf = 0; nf < 4; nf++)
            #pragma unroll
            for (int i = 0; i < 4; i++) c[mf][nf][i] = 0.f;

    ISSUE(0, 0);
    ISSUE(1, 1);

    for (int ch = 0; ch < 32; ch++) {
        const int s = ch & 1;
        if (ch + 2 < 32) { CP_WAIT1(); } else { CP_WAIT0(); }
        __syncthreads();

        const __half* A0 = As + s * GSTH;
        const __half* B0 = Bs + s * GSTH;
        #pragma unroll
        for (int kk = 0; kk < 32; kk += 16) {
            uint32_t a[4][4], b[4][2];
            #pragma unroll
            for (int mf = 0; mf < 4; mf++) {
                const int mr = m0 + mf * 16 + g;
                a[mf][0] = *(const uint32_t*)&A0[(mr    ) * 40 + kk + 2 * tig];
                a[mf][1] = *(const uint32_t*)&A0[(mr + 8) * 40 + kk + 2 * tig];
                a[mf][2] = *(const uint32_t*)&A0[(mr    ) * 40 + kk + 2 * tig + 8];
                a[mf][3] = *(const uint32_t*)&A0[(mr + 8) * 40 + kk + 2 * tig + 8];
            }
            #pragma unroll
            for (int nf = 0; nf < 4; nf++) {
                const int nr = n0 + nf * 8 + g;
                b[nf][0] = *(const uint32_t*)&B0[nr * 40 + kk + 2 * tig];
                b[nf][1] = *(const uint32_t*)&B0[nr * 40 + kk + 2 * tig + 8];
            }
            #pragma unroll
            for (int mf = 0; mf < 4; mf++)
                #pragma unroll
                for (int nf = 0; nf < 4; nf++)
                    mma_f16(c[mf][nf], a[mf], b[nf]);
        }
        __syncthreads();
        if (ch + 2 < 32) ISSUE(s, ch + 2);
    }

    #pragma unroll
    for (int mf = 0; mf < 4; mf++) {
        #pragma unroll
        for (int nf = 0; nf < 4; nf++) {
            const int col = bn * 128 + n0 + nf * 8 + 2 * tig;
            const float bz0 = bias[col], bz1 = bias[col + 1];
            #pragma unroll
            for (int half_ = 0; half_ < 2; half_++) {
                const int m = bm * 128 + m0 + mf * 16 + g + half_ * 8;
                const float vx = c[mf][nf][half_ * 2 + 0] + bz0;
                const float vy = c[mf][nf][half_ * 2 + 1] + bz1;
                if (OUT_HEADED) {
                    const int bb = m >> 11, t = m & 2047;
                    const int h = col >> 6, d = col & 63;
                    __half* Y = (__half*)Yv;
                    *(uint32_t*)&Y[(((size_t)(bb * NHEADS + h) * SEQ) + t) * HDIM + d] =
                        pack_h2(vx, vy);
                } else {
                    float* Y = (float*)Yv;
                    float2 v = { vx, vy };
                    *(float2*)&Y[(size_t)m * DMODEL + col] = v;
                }
            }
        }
    }
    #undef ISSUE
}

// ---------------------------------------------------------------------------
// fp16 tensor-core causal flash attention. Grid (16, 64), 256 thr = 8 warps;
// warp owns 16 q-rows. Q tile 128, KV tile 64. V transposed in smem.
// Strides 72 halves (word ≡ 36·g+tig mod 32, conflict-free).
// ---------------------------------------------------------------------------
#define FPS 72
#define FLASH_SMEM ((128*FPS + 64*FPS + 64*FPS) * 2)   // 36864 B

__global__ __launch_bounds__(256, 2)
void flash_mma()
{
    extern __shared__ __half smh[];
    __half* Ps = smh;                 // [128][72] Q staging, then P
    __half* Ks = smh + 128 * FPS;     // [64][72]  K rows [n][k]
    __half* Vt = Ks + 64 * FPS;       // [64][72]  V transposed [d][t]

    const int tid = threadIdx.x;
    const int wid = tid >> 5, lane = tid & 31;
    const int g = lane >> 2, tig = lane & 3;
    const int qb = blockIdx.x, bh = blockIdx.y;
    const int m0 = wid * 16;
    const int r0 = m0 + g, r1 = m0 + g + 8;
    const int qg0 = qb * 128 + r0, qg1 = qb * 128 + r1;

    // Stage Q tile: 128 rows x 64 halves = 1024 x 16B chunks
    {
        const __half* Qb = g_Qh + ((size_t)bh * SEQ + qb * 128) * HDIM;
        #pragma unroll
        for (int j = 0; j < 4; j++) {
            const int c = tid + j * 256;
            const int r = c >> 3, o = (c & 7) * 8;
            *(uint4*)(Ps + r * FPS + o) = *(const uint4*)(Qb + (size_t)r * HDIM + o);
        }
    }
    __syncthreads();

    // Q fragments (4 k-steps of 16), register-resident
    uint32_t qa[4][4];
    #pragma unroll
    for (int kf = 0; kf < 4; kf++) {
        qa[kf][0] = *(uint32_t*)&Ps[r0 * FPS + kf * 16 + 2 * tig];
        qa[kf][1] = *(uint32_t*)&Ps[r1 * FPS + kf * 16 + 2 * tig];
        qa[kf][2] = *(uint32_t*)&Ps[r0 * FPS + kf * 16 + 2 * tig + 8];
        qa[kf][3] = *(uint32_t*)&Ps[r1 * FPS + kf * 16 + 2 * tig + 8];
    }

    float o[8][4];
    #pragma unroll
    for (int nf = 0; nf < 8; nf++)
        #pragma unroll
        for (int i = 0; i < 4; i++) o[nf][i] = 0.f;
    float mr0 = -INFINITY, mr1 = -INFINITY, l0 = 0.f, l1 = 0.f;

    const int ktiles = (qb + 1) * 2;
    const float scale = 0.125f;   // 1/sqrt(64)

    for (int kt = 0; kt < ktiles; kt++) {
        __syncthreads();
        // Stage K rows (512 x 16B chunks) + V transposed
        {
            const __half* Kt = g_Kh + ((size_t)bh * SEQ + kt * 64) * HDIM;
            #pragma unroll
            for (int j = 0; j < 2; j++) {
                const int c = tid + j * 256;
                const int r = c >> 3, off = (c & 7) * 8;
                *(uint4*)(Ks + r * FPS + off) = *(const uint4*)(Kt + (size_t)r * HDIM + off);
            }
            // V: thread loads 16 contiguous d-halves of row t, scatters to Vt[d][t]
            const __half* Vsrc = g_Vh + ((size_t)bh * SEQ + kt * 64) * HDIM;
            const int t = tid & 63, d0 = (tid >> 6) * 16;
            uint4 v0 = *(const uint4*)(Vsrc + (size_t)t * HDIM + d0);
            uint4 v1 = *(const uint4*)(Vsrc + (size_t)t * HDIM + d0 + 8);
            const __half* hv0 = (const __half*)&v0;
            const __half* hv1 = (const __half*)&v1;
            #pragma unroll
            for (int jj = 0; jj < 8; jj++) {
                Vt[(d0 + jj)     * FPS + t] = hv0[jj];
                Vt[(d0 + jj + 8) * FPS + t] = hv1[jj];
            }
        }
        __syncthreads();

        // S = Q @ K^T
        float s[8][4];
        #pragma unroll
        for (int nf = 0; nf < 8; nf++)
            #pragma unroll
            for (int i = 0; i < 4; i++) s[nf][i] = 0.f;

        #pragma unroll
        for (int kf = 0; kf < 4; kf++) {
            #pragma unroll
            for (int nf = 0; nf < 8; nf++) {
                uint32_t b[2];
                b[0] = *(uint32_t*)&Ks[(nf * 8 + g) * FPS + kf * 16 + 2 * tig];
                b[1] = *(uint32_t*)&Ks[(nf * 8 + g) * FPS + kf * 16 + 2 * tig + 8];
                mma_f16(s[nf], qa[kf], b);
            }
        }

        const bool diag = (kt >= 2 * qb);
        #pragma unroll
        for (int nf = 0; nf < 8; nf++) {
            const int cb = kt * 64 + nf * 8 + 2 * tig;
            s[nf][0] *= scale; s[nf][1] *= scale;
            s[nf][2] *= scale; s[nf][3] *= scale;
            if (diag) {
                if (cb     > qg0) s[nf][0] = -INFINITY;
                if (cb + 1 > qg0) s[nf][1] = -INFINITY;
                if (cb     > qg1) s[nf][2] = -INFINITY;
                if (cb + 1 > qg1) s[nf][3] = -INFINITY;
            }
        }

        float mn0 = s[0][0], mn1 = s[0][2];
        #pragma unroll
        for (int nf = 0; nf < 8; nf++) {
            mn0 = fmaxf(mn0, fmaxf(s[nf][0], s[nf][1]));
            mn1 = fmaxf(mn1, fmaxf(s[nf][2], s[nf][3]));
        }
        mn0 = fmaxf(mn0, __shfl_xor_sync(0xffffffffu, mn0, 1));
        mn0 = fmaxf(mn0, __shfl_xor_sync(0xffffffffu, mn0, 2));
        mn1 = fmaxf(mn1, __shfl_xor_sync(0xffffffffu, mn1, 1));
        mn1 = fmaxf(mn1, __shfl_xor_sync(0xffffffffu, mn1, 2));
        mn0 = fmaxf(mr0, mn0);
        mn1 = fmaxf(mr1, mn1);

        const float cr0 = __expf(mr0 - mn0);
        const float cr1 = __expf(mr1 - mn1);
        mr0 = mn0; mr1 = mn1;
        #pragma unroll
        for (int nf = 0; nf < 8; nf++) {
            o[nf][0] *= cr0; o[nf][1] *= cr0;
            o[nf][2] *= cr1; o[nf][3] *= cr1;
        }

        float ps0 = 0.f, ps1 = 0.f;
        #pragma unroll
        for (int nf = 0; nf < 8; nf++) {
            const float p0 = __expf(s[nf][0] - mn0);
            const float p1 = __expf(s[nf][1] - mn0);
            const float p2 = __expf(s[nf][2] - mn1);
            const float p3 = __expf(s[nf][3] - mn1);
            ps0 += p0 + p1; ps1 += p2 + p3;
            *(uint32_t*)&Ps[r0 * FPS + nf * 8 + 2 * tig] = pack_h2(p0, p1);
            *(uint32_t*)&Ps[r1 * FPS + nf * 8 + 2 * tig] = pack_h2(p2, p3);
        }
        ps0 += __shfl_xor_sync(0xffffffffu, ps0, 1);
        ps0 += __shfl_xor_sync(0xffffffffu, ps0, 2);
        ps1 += __shfl_xor_sync(0xffffffffu, ps1, 1);
        ps1 += __shfl_xor_sync(0xffffffffu, ps1, 2);
        l0 = l0 * cr0 + ps0;
        l1 = l1 * cr1 + ps1;

        // O += P @ V  (P rows warp-private; Vt is [d][t])
        #pragma unroll
        for (int kf = 0; kf < 4; kf++) {
            uint32_t pa[4];
            pa[0] = *(uint32_t*)&Ps[r0 * FPS + kf * 16 + 2 * tig];
            pa[1] = *(uint32_t*)&Ps[r1 * FPS + kf * 16 + 2 * tig];
            pa[2] = *(uint32_t*)&Ps[r0 * FPS + kf * 16 + 2 * tig + 8];
            pa[3] = *(uint32_t*)&Ps[r1 * FPS + kf * 16 + 2 * tig + 8];
            #pragma unroll
            for (int nf = 0; nf < 8; nf++) {
                uint32_t b[2];
                b[0] = *(uint32_t*)&Vt[(nf * 8 + g) * FPS + kf * 16 + 2 * tig];
                b[1] = *(uint32_t*)&Vt[(nf * 8 + g) * FPS + kf * 16 + 2 * tig + 8];
                mma_f16(o[nf], pa, b);
            }
        }
    }

    // Epilogue: normalize, write half to g_Ah [b, t, h*64+d]
    const float i0 = 1.f / l0, i1 = 1.f / l1;
    const int bb = bh >> 4, h = bh & 15;
    __half* A0 = g_Ah + ((size_t)(bb * SEQ) + qg0) * DMODEL + h * HDIM;
    __half* A1 = g_Ah + ((size_t)(bb * SEQ) + qg1) * DMODEL + h * HDIM;
    #pragma unroll
    for (int nf = 0; nf < 8; nf++) {
        *(uint32_t*)(A0 + nf * 8 + 2 * tig) = pack_h2(o[nf][0] * i0, o[nf][1] * i0);
        *(uint32_t*)(A1 + nf * 8 + 2 * tig) = pack_h2(o[nf][2] * i1, o[nf][3] * i1);
    }
}

// ---------------------------------------------------------------------------
extern "C" void kernel_launch(void* const* d_in, const int* in_sizes, int n_in,
                              void* d_out, int out_size)
{
    const float* x  = (const float*)d_in[0];
    const float* Wq = (const float*)d_in[2];
    const float* bq = (const float*)d_in[3];
    const float* Wk = (const float*)d_in[4];
    const float* bk = (const float*)d_in[5];
    const float* Wv = (const float*)d_in[6];
    const float* bv = (const float*)d_in[7];
    const float* Wo = (const float*)d_in[8];
    const float* bo = (const float*)d_in[9];
    float* out = (float*)d_out;

    __half *Qp, *Kp, *Vp, *Ap, *Wt, *Xh;
    cudaGetSymbolAddress((void**)&Qp, g_Qh);
    cudaGetSymbolAddress((void**)&Kp, g_Kh);
    cudaGetSymbolAddress((void**)&Vp, g_Vh);
    cudaGetSymbolAddress((void**)&Ap, g_Ah);
    cudaGetSymbolAddress((void**)&Wt, g_Wth);
    cudaGetSymbolAddress((void**)&Xh, g_Xh);

    cudaFuncSetAttribute(flash_mma, cudaFuncAttributeMaxDynamicSharedMemorySize,
                         FLASH_SMEM);
    cudaFuncSetAttribute(gemm_pipe<1>, cudaFuncAttributeMaxDynamicSharedMemorySize,
                         GP_SMEM);
    cudaFuncSetAttribute(gemm_pipe<0>, cudaFuncAttributeMaxDynamicSharedMemorySize,
                         GP_SMEM);

    tohalf_kernel<<<(MROWS * DMODEL) / (256 * 8), 256>>>((const float4*)x, (uint4*)Xh);
    dim3 tgrid(32, 32), tblk(32, 8);
    transpose_kernel<<<tgrid, tblk>>>(Wq, Wt + 0u * 1024u * 1024u);
    transpose_kernel<<<tgrid, tblk>>>(Wk, Wt + 1u * 1024u * 1024u);
    transpose_kernel<<<tgrid, tblk>>>(Wv, Wt + 2u * 1024u * 1024u);
    transpose_kernel<<<tgrid, tblk>>>(Wo, Wt + 3u * 1024u * 1024u);

    // Fused QKV projection (z selects weight/bias/output)
    dim3 qkvgrid(DMODEL / 128, MROWS / 128, 3);   // (8, 64, 3)
    gemm_pipe<1><<<qkvgrid, 256, GP_SMEM>>>(Xh, Wt, bq, bk, bv, Qp, Kp, Vp);

    dim3 fgrid(SEQ / 128, BATCH * NHEADS);        // (16, 64)
    flash_mma<<<fgrid, 256, FLASH_SMEM>>>();

    dim3 ogrid(DMODEL / 128, MROWS / 128, 1);
    gemm_pipe<0><<<ogrid, 256, GP_SMEM>>>(Ap, Wt + 3u * 1024u * 1024u,
                                          bo, bo, bo, out, out, out);
}

// round 14
// speedup vs baseline: 8.3879x; 1.1751x over previous
#include <cuda_runtime.h>
#include <cuda_fp16.h>
#include <math.h>
#include <stdint.h>

#define BATCH 4
#define SEQ   2048
#define DMODEL 1024
#define NHEADS 16
#define HDIM  64
#define MROWS (BATCH*SEQ)   // 8192

// Scratch (no cudaMalloc allowed) — all fp16
__device__ __half g_Qh[(size_t)BATCH*NHEADS*SEQ*HDIM];
__device__ __half g_Kh[(size_t)BATCH*NHEADS*SEQ*HDIM];
__device__ __half g_Vh[(size_t)BATCH*NHEADS*SEQ*HDIM];
__device__ __half g_Ah[(size_t)BATCH*SEQ*DMODEL];
__device__ __half g_Xh[(size_t)MROWS*DMODEL];
__device__ __half g_Wth[4u*1024u*1024u];     // 4 transposed weights [N,K] fp16

__device__ __forceinline__ uint32_t smem_u32(const void* p) {
    uint32_t a;
    asm("{ .reg .u64 t; cvta.to.shared.u64 t, %1; cvt.u32.u64 %0, t; }"
        : "=r"(a) : "l"(p));
    return a;
}
__device__ __forceinline__ void mma_f16(float* c, const uint32_t* a, const uint32_t* b) {
    asm volatile(
        "mma.sync.aligned.m16n8k16.row.col.f32.f16.f16.f32 "
        "{%0,%1,%2,%3}, {%4,%5,%6,%7}, {%8,%9}, {%0,%1,%2,%3};"
        : "+f"(c[0]), "+f"(c[1]), "+f"(c[2]), "+f"(c[3])
        : "r"(a[0]), "r"(a[1]), "r"(a[2]), "r"(a[3]), "r"(b[0]), "r"(b[1]));
}
__device__ __forceinline__ uint32_t pack_h2(float x, float y) {
    __half2 h = __floats2half2_rn(x, y);
    return *(uint32_t*)&h;
}
#define LDSM_X4(r0, r1, r2, r3, addr) \
    asm volatile("ldmatrix.sync.aligned.m8n8.x4.shared.b16 {%0,%1,%2,%3}, [%4];" \
        : "=r"(r0), "=r"(r1), "=r"(r2), "=r"(r3) : "r"(addr))
#define LDSM_X4_T(r0, r1, r2, r3, addr) \
    asm volatile("ldmatrix.sync.aligned.m8n8.x4.trans.shared.b16 {%0,%1,%2,%3}, [%4];" \
        : "=r"(r0), "=r"(r1), "=r"(r2), "=r"(r3) : "r"(addr))
#define CP_ASYNC16(dst, src) \
    asm volatile("cp.async.cg.shared.global [%0], [%1], 16;" :: "r"(dst), "l"(src))
#define CP_COMMIT() asm volatile("cp.async.commit_group;" ::: "memory")
#define CP_WAIT1()  asm volatile("cp.async.wait_group 1;"  ::: "memory")
#define CP_WAIT0()  asm volatile("cp.async.wait_group 0;"  ::: "memory")

// ---------------------------------------------------------------------------
// Convert x to fp16. 8 floats -> 8 halves per thread.
// ---------------------------------------------------------------------------
__global__ __launch_bounds__(256)
void tohalf_kernel(const float4* __restrict__ in, uint4* __restrict__ out)
{
    const int i = blockIdx.x * 256 + threadIdx.x;
    float4 v0 = in[2 * i], v1 = in[2 * i + 1];
    uint4 o;
    o.x = pack_h2(v0.x, v0.y); o.y = pack_h2(v0.z, v0.w);
    o.z = pack_h2(v1.x, v1.y); o.w = pack_h2(v1.z, v1.w);
    out[i] = o;
}

// ---------------------------------------------------------------------------
// Fused transpose+halve of all 4 weights: z selects source.
// ---------------------------------------------------------------------------
__global__ __launch_bounds__(256)
void transpose4_kernel(const float* __restrict__ W0, const float* __restrict__ W1,
                       const float* __restrict__ W2, const float* __restrict__ W3,
                       __half* __restrict__ WtBase)
{
    __shared__ float t[32][33];
    const int z = blockIdx.z;
    const float* W = (z == 0) ? W0 : (z == 1) ? W1 : (z == 2) ? W2 : W3;
    __half* Wt = WtBase + (size_t)z * 1024u * 1024u;
    const int x0 = blockIdx.x * 32, y0 = blockIdx.y * 32;
    const int tx = threadIdx.x, ty = threadIdx.y;
    #pragma unroll
    for (int i = 0; i < 32; i += 8)
        t[ty + i][tx] = W[(size_t)(y0 + ty + i) * 1024 + x0 + tx];
    __syncthreads();
    #pragma unroll
    for (int i = 0; i < 32; i += 8)
        Wt[(size_t)(x0 + ty + i) * 1024 + y0 + tx] = __float2half_rn(t[tx][ty + i]);
}

// ---------------------------------------------------------------------------
// Pipelined fp16 GEMM (cp.async 2-stage, ldmatrix frags): Y = X @ W + bias.
// CTA 128x128x32, 256 thr, warp 64x32 of m16n8k16. Stride 40 halves.
// ---------------------------------------------------------------------------
#define GSTH (128*40)                 // halves per tile per stage
#define GP_SMEM (4*GSTH*2)            // 40960 B

template<int OUT_HEADED>
__global__ __launch_bounds__(256, 2)
void gemm_pipe(const __half* __restrict__ X, const __half* __restrict__ WtBase,
               const float* b0, const float* b1, const float* b2,
               void* y0, void* y1, void* y2)
{
    extern __shared__ __half smh[];
    __half* As = smh;              // [2][128][40]
    __half* Bs = smh + 2 * GSTH;   // [2][128][40]

    const int z = blockIdx.z;
    const __half* Bt   = WtBase + (size_t)z * 1024u * 1024u;
    const float*  bias = (z == 0) ? b0 : (z == 1) ? b1 : b2;
    void*         Yv   = (z == 0) ? y0 : (z == 1) ? y1 : y2;

    const int tid = threadIdx.x;
    const int wid = tid >> 5, lane = tid & 31;
    const int bn = blockIdx.x, bm = blockIdx.y;
    const int warp_m = wid >> 2, warp_n = wid & 3;
    const int g = lane >> 2, tig = lane & 3;
    const int m0 = warp_m * 64, n0 = warp_n * 32;

    const __half* Xb  = X  + (size_t)(bm * 128) * DMODEL;
    const __half* Btb = Bt + (size_t)(bn * 128) * DMODEL;

    // ldmatrix base addresses (byte, shared space)
    const uint32_t As_u = smem_u32(As), Bs_u = smem_u32(Bs);
    const uint32_t a_base = As_u + ((m0 + (lane & 15)) * 40 + (lane >> 4) * 8) * 2;
    const uint32_t b_base0 = Bs_u +
        ((n0 + 0  + ((lane >> 4) & 1) * 8 + (lane & 7)) * 40 + ((lane >> 3) & 1) * 8) * 2;
    const uint32_t b_base1 = Bs_u +
        ((n0 + 16 + ((lane >> 4) & 1) * 8 + (lane & 7)) * 40 + ((lane >> 3) & 1) * 8) * 2;

    #define ISSUE(stage, chunk) do { \
        const int _k0 = (chunk) * 32; \
        _Pragma("unroll") \
        for (int _j = 0; _j < 2; _j++) { \
            const int _c = tid + _j * 256; \
            const int _r = _c >> 2, _o = (_c & 3) * 8; \
            CP_ASYNC16(As_u + ((stage) * GSTH + _r * 40 + _o) * 2, \
                       Xb  + (size_t)_r * DMODEL + _k0 + _o); \
            CP_ASYNC16(Bs_u + ((stage) * GSTH + _r * 40 + _o) * 2, \
                       Btb + (size_t)_r * DMODEL + _k0 + _o); \
        } \
        CP_COMMIT(); \
    } while (0)

    float c[4][4][4];
    #pragma unroll
    for (int mf = 0; mf < 4; mf++)
        #pragma unroll
        for (int nf = 0; nf < 4; nf++)
            #pragma unroll
            for (int i = 0; i < 4; i++) c[mf][nf][i] = 0.f;

    ISSUE(0, 0);
    ISSUE(1, 1);

    for (int ch = 0; ch < 32; ch++) {
        const int s = ch & 1;
        if (ch + 2 < 32) { CP_WAIT1(); } else { CP_WAIT0(); }
        __syncthreads();

        const uint32_t soff = (uint32_t)(s * GSTH) * 2;
        #pragma unroll
        for (int kk = 0; kk < 32; kk += 16) {
            uint32_t a[4][4], b[4][2];
            #pragma unroll
            for (int mf = 0; mf < 4; mf++)
                LDSM_X4(a[mf][0], a[mf][1], a[mf][2], a[mf][3],
                        a_base + soff + kk * 2 + mf * (16 * 40 * 2));
            LDSM_X4(b[0][0], b[0][1], b[1][0], b[1][1], b_base0 + soff + kk * 2);
            LDSM_X4(b[2][0], b[2][1], b[3][0], b[3][1], b_base1 + soff + kk * 2);
            #pragma unroll
            for (int mf = 0; mf < 4; mf++)
                #pragma unroll
                for (int nf = 0; nf < 4; nf++)
                    mma_f16(c[mf][nf], a[mf], b[nf]);
        }
        __syncthreads();
        if (ch + 2 < 32) ISSUE(s, ch + 2);
    }

    #pragma unroll
    for (int mf = 0; mf < 4; mf++) {
        #pragma unroll
        for (int nf = 0; nf < 4; nf++) {
            const int col = bn * 128 + n0 + nf * 8 + 2 * tig;
            const float bz0 = bias[col], bz1 = bias[col + 1];
            #pragma unroll
            for (int half_ = 0; half_ < 2; half_++) {
                const int m = bm * 128 + m0 + mf * 16 + g + half_ * 8;
                const float vx = c[mf][nf][half_ * 2 + 0] + bz0;
                const float vy = c[mf][nf][half_ * 2 + 1] + bz1;
                if (OUT_HEADED) {
                    const int bb = m >> 11, t = m & 2047;
                    const int h = col >> 6, d = col & 63;
                    __half* Y = (__half*)Yv;
                    *(uint32_t*)&Y[(((size_t)(bb * NHEADS + h) * SEQ) + t) * HDIM + d] =
                        pack_h2(vx, vy);
                } else {
                    float* Y = (float*)Yv;
                    float2 v = { vx, vy };
                    *(float2*)&Y[(size_t)m * DMODEL + col] = v;
                }
            }
        }
    }
    #undef ISSUE
}

// ---------------------------------------------------------------------------
// fp16 flash attention: cp.async 2-stage K/V, ldmatrix frags, V via .trans.
// Grid (16, 64), 256 thr = 8 warps; warp owns 16 q-rows. KV tile 64.
// Smem stride 72 halves. Ps [128][72]; Ks/Vs [2][64][72] (V in [t][d]).
// ---------------------------------------------------------------------------
#define FPS 72
#define KVSZ (64*FPS)
#define FLASH_SMEM ((128*FPS + 4*KVSZ) * 2)   // 55296 B

__global__ __launch_bounds__(256, 2)
void flash_mma()
{
    extern __shared__ __half smh[];
    __half* Ps = smh;                    // [128][72] Q staging, then P
    __half* Ks = smh + 128 * FPS;        // [2][64][72] K rows [n][k]
    __half* Vs = Ks + 2 * KVSZ;          // [2][64][72] V rows [t][d]

    const int tid = threadIdx.x;
    const int wid = tid >> 5, lane = tid & 31;
    const int g = lane >> 2, tig = lane & 3;
    const int qb = blockIdx.x, bh = blockIdx.y;
    const int m0 = wid * 16;
    const int r0 = m0 + g, r1 = m0 + g + 8;
    const int qg0 = qb * 128 + r0, qg1 = qb * 128 + r1;

    const uint32_t Ps_u = smem_u32(Ps), Ks_u = smem_u32(Ks), Vs_u = smem_u32(Vs);
    // A-frag base (Q and P share layout): rows wid*16+(lane&15), koff (lane>>4)*8
    const uint32_t pa_base = Ps_u + ((m0 + (lane & 15)) * FPS + (lane >> 4) * 8) * 2;
    // K b-frag bases for nf pairs p=0..3
    const uint32_t kb_row = ((lane >> 4) & 1) * 8 + (lane & 7);
    const uint32_t kb_koff = ((lane >> 3) & 1) * 8;
    // V (.trans) base: rows t = kf*16 + ((lane>>3)&1)*8 + (lane&7); col d = p*16+(lane>>4)*8
    const uint32_t vt_row = ((lane >> 3) & 1) * 8 + (lane & 7);
    const uint32_t vt_col = (lane >> 4) * 8;

    const __half* Kb = g_Kh + (size_t)bh * SEQ * HDIM;
    const __half* Vb = g_Vh + (size_t)bh * SEQ * HDIM;

    #define ISSUE_KV(stage, kt_) do { \
        const __half* _ks = Kb + (size_t)(kt_) * 64 * HDIM; \
        const __half* _vs = Vb + (size_t)(kt_) * 64 * HDIM; \
        _Pragma("unroll") \
        for (int _j = 0; _j < 2; _j++) { \
            const int _c = tid + _j * 256; \
            const int _r = _c >> 3, _o = (_c & 7) * 8; \
            CP_ASYNC16(Ks_u + ((stage) * KVSZ + _r * FPS + _o) * 2, _ks + _r * HDIM + _o); \
            CP_ASYNC16(Vs_u + ((stage) * KVSZ + _r * FPS + _o) * 2, _vs + _r * HDIM + _o); \
        } \
        CP_COMMIT(); \
    } while (0)

    // Stage Q tile (plain loads, once)
    {
        const __half* Qb = g_Qh + ((size_t)bh * SEQ + qb * 128) * HDIM;
        #pragma unroll
        for (int j = 0; j < 4; j++) {
            const int c = tid + j * 256;
            const int r = c >> 3, o = (c & 7) * 8;
            *(uint4*)(Ps + r * FPS + o) = *(const uint4*)(Qb + (size_t)r * HDIM + o);
        }
    }
    const int ktiles = (qb + 1) * 2;
    ISSUE_KV(0, 0);
    __syncthreads();

    // Q fragments (4 k-steps of 16), register-resident
    uint32_t qa[4][4];
    #pragma unroll
    for (int kf = 0; kf < 4; kf++)
        LDSM_X4(qa[kf][0], qa[kf][1], qa[kf][2], qa[kf][3], pa_base + kf * 16 * 2);

    float o[8][4];
    #pragma unroll
    for (int nf = 0; nf < 8; nf++)
        #pragma unroll
        for (int i = 0; i < 4; i++) o[nf][i] = 0.f;
    float mr0 = -INFINITY, mr1 = -INFINITY, l0 = 0.f, l1 = 0.f;

    const float scale = 0.125f;   // 1/sqrt(64)

    for (int kt = 0; kt < ktiles; kt++) {
        const int s = kt & 1;
        if (kt + 1 < ktiles) { ISSUE_KV(s ^ 1, kt + 1); CP_WAIT1(); }
        else                 { CP_WAIT0(); }
        __syncthreads();

        const uint32_t ksoff = (uint32_t)(s * KVSZ) * 2;

        // S = Q @ K^T
        float sacc[8][4];
        #pragma unroll
        for (int nf = 0; nf < 8; nf++)
            #pragma unroll
            for (int i = 0; i < 4; i++) sacc[nf][i] = 0.f;

        #pragma unroll
        for (int kf = 0; kf < 4; kf++) {
            #pragma unroll
            for (int p = 0; p < 4; p++) {
                uint32_t b[2][2];
                LDSM_X4(b[0][0], b[0][1], b[1][0], b[1][1],
                        Ks_u + ksoff + ((p * 16 + kb_row) * FPS + kf * 16 + kb_koff) * 2);
                mma_f16(sacc[2 * p],     qa[kf], b[0]);
                mma_f16(sacc[2 * p + 1], qa[kf], b[1]);
            }
        }

        const bool diag = (kt >= 2 * qb);
        #pragma unroll
        for (int nf = 0; nf < 8; nf++) {
            const int cb = kt * 64 + nf * 8 + 2 * tig;
            sacc[nf][0] *= scale; sacc[nf][1] *= scale;
            sacc[nf][2] *= scale; sacc[nf][3] *= scale;
            if (diag) {
                if (cb     > qg0) sacc[nf][0] = -INFINITY;
                if (cb + 1 > qg0) sacc[nf][1] = -INFINITY;
                if (cb     > qg1) sacc[nf][2] = -INFINITY;
                if (cb + 1 > qg1) sacc[nf][3] = -INFINITY;
            }
        }

        float mn0 = sacc[0][0], mn1 = sacc[0][2];
        #pragma unroll
        for (int nf = 0; nf < 8; nf++) {
            mn0 = fmaxf(mn0, fmaxf(sacc[nf][0], sacc[nf][1]));
            mn1 = fmaxf(mn1, fmaxf(sacc[nf][2], sacc[nf][3]));
        }
        mn0 = fmaxf(mn0, __shfl_xor_sync(0xffffffffu, mn0, 1));
        mn0 = fmaxf(mn0, __shfl_xor_sync(0xffffffffu, mn0, 2));
        mn1 = fmaxf(mn1, __shfl_xor_sync(0xffffffffu, mn1, 1));
        mn1 = fmaxf(mn1, __shfl_xor_sync(0xffffffffu, mn1, 2));
        mn0 = fmaxf(mr0, mn0);
        mn1 = fmaxf(mr1, mn1);

        const float cr0 = __expf(mr0 - mn0);
        const float cr1 = __expf(mr1 - mn1);
        mr0 = mn0; mr1 = mn1;
        #pragma unroll
        for (int nf = 0; nf < 8; nf++) {
            o[nf][0] *= cr0; o[nf][1] *= cr0;
            o[nf][2] *= cr1; o[nf][3] *= cr1;
        }

        float ps0 = 0.f, ps1 = 0.f;
        #pragma unroll
        for (int nf = 0; nf < 8; nf++) {
            const float p0 = __expf(sacc[nf][0] - mn0);
            const float p1 = __expf(sacc[nf][1] - mn0);
            const float p2 = __expf(sacc[nf][2] - mn1);
            const float p3 = __expf(sacc[nf][3] - mn1);
            ps0 += p0 + p1; ps1 += p2 + p3;
            *(uint32_t*)&Ps[r0 * FPS + nf * 8 + 2 * tig] = pack_h2(p0, p1);
            *(uint32_t*)&Ps[r1 * FPS + nf * 8 + 2 * tig] = pack_h2(p2, p3);
        }
        ps0 += __shfl_xor_sync(0xffffffffu, ps0, 1);
        ps0 += __shfl_xor_sync(0xffffffffu, ps0, 2);
        ps1 += __shfl_xor_sync(0xffffffffu, ps1, 1);
        ps1 += __shfl_xor_sync(0xffffffffu, ps1, 2);
        l0 = l0 * cr0 + ps0;
        l1 = l1 * cr1 + ps1;
        __syncwarp();

        // O += P @ V  (P warp-private rows; V [t][d] loaded with ldmatrix.trans)
        const uint32_t vsoff = (uint32_t)(s * KVSZ) * 2;
        #pragma unroll
        for (int kf = 0; kf < 4; kf++) {
            uint32_t pa[4];
            LDSM_X4(pa[0], pa[1], pa[2], pa[3], pa_base + kf * 16 * 2);
            #pragma unroll
            for (int p = 0; p < 4; p++) {
                uint32_t b[2][2];
                LDSM_X4_T(b[0][0], b[0][1], b[1][0], b[1][1],
                          Vs_u + vsoff + ((kf * 16 + vt_row) * FPS + p * 16 + vt_col) * 2);
                mma_f16(o[2 * p],     pa, b[0]);
                mma_f16(o[2 * p + 1], pa, b[1]);
            }
        }
        __syncthreads();
    }

    // Epilogue: normalize, write half to g_Ah [b, t, h*64+d]
    const float i0 = 1.f / l0, i1 = 1.f / l1;
    const int bb = bh >> 4, h = bh & 15;
    __half* A0 = g_Ah + ((size_t)(bb * SEQ) + qg0) * DMODEL + h * HDIM;
    __half* A1 = g_Ah + ((size_t)(bb * SEQ) + qg1) * DMODEL + h * HDIM;
    #pragma unroll
    for (int nf = 0; nf < 8; nf++) {
        *(uint32_t*)(A0 + nf * 8 + 2 * tig) = pack_h2(o[nf][0] * i0, o[nf][1] * i0);
        *(uint32_t*)(A1 + nf * 8 + 2 * tig) = pack_h2(o[nf][2] * i1, o[nf][3] * i1);
    }
    #undef ISSUE_KV
}

// ---------------------------------------------------------------------------
extern "C" void kernel_launch(void* const* d_in, const int* in_sizes, int n_in,
                              void* d_out, int out_size)
{
    const float* x  = (const float*)d_in[0];
    const float* Wq = (const float*)d_in[2];
    const float* bq = (const float*)d_in[3];
    const float* Wk = (const float*)d_in[4];
    const float* bk = (const float*)d_in[5];
    const float* Wv = (const float*)d_in[6];
    const float* bv = (const float*)d_in[7];
    const float* Wo = (const float*)d_in[8];
    const float* bo = (const float*)d_in[9];
    float* out = (float*)d_out;

    __half *Qp, *Kp, *Vp, *Ap, *Wt, *Xh;
    cudaGetSymbolAddress((void**)&Qp, g_Qh);
    cudaGetSymbolAddress((void**)&Kp, g_Kh);
    cudaGetSymbolAddress((void**)&Vp, g_Vh);
    cudaGetSymbolAddress((void**)&Ap, g_Ah);
    cudaGetSymbolAddress((void**)&Wt, g_Wth);
    cudaGetSymbolAddress((void**)&Xh, g_Xh);

    cudaFuncSetAttribute(flash_mma, cudaFuncAttributeMaxDynamicSharedMemorySize,
                         FLASH_SMEM);
    cudaFuncSetAttribute(gemm_pipe<1>, cudaFuncAttributeMaxDynamicSharedMemorySize,
                         GP_SMEM);
    cudaFuncSetAttribute(gemm_pipe<0>, cudaFuncAttributeMaxDynamicSharedMemorySize,
                         GP_SMEM);

    tohalf_kernel<<<(MROWS * DMODEL) / (256 * 8), 256>>>((const float4*)x, (uint4*)Xh);
    dim3 tgrid(32, 32, 4), tblk(32, 8);
    transpose4_kernel<<<tgrid, tblk>>>(Wq, Wk, Wv, Wo, Wt);

    // Fused QKV projection (z selects weight/bias/output)
    dim3 qkvgrid(DMODEL / 128, MROWS / 128, 3);   // (8, 64, 3)
    gemm_pipe<1><<<qkvgrid, 256, GP_SMEM>>>(Xh, Wt, bq, bk, bv, Qp, Kp, Vp);

    dim3 fgrid(SEQ / 128, BATCH * NHEADS);        // (16, 64)
    flash_mma<<<fgrid, 256, FLASH_SMEM>>>();

    dim3 ogrid(DMODEL / 128, MROWS / 128, 1);
    gemm_pipe<0><<<ogrid, 256, GP_SMEM>>>(Ap, Wt + 3u * 1024u * 1024u,
                                          bo, bo, bo, out, out, out);
}

// round 15
// speedup vs baseline: 8.8729x; 1.0578x over previous
#include <cuda_runtime.h>
#include <cuda_fp16.h>
#include <math.h>
#include <stdint.h>

#define BATCH 4
#define SEQ   2048
#define DMODEL 1024
#define NHEADS 16
#define HDIM  64
#define MROWS (BATCH*SEQ)   // 8192

// 1/sqrt(64) * log2(e), folded into Q at projection time
#define QSCALE 0.18033688011112042f

// Scratch (no cudaMalloc allowed) — all fp16
__device__ __half g_Qh[(size_t)BATCH*NHEADS*SEQ*HDIM];
__device__ __half g_Kh[(size_t)BATCH*NHEADS*SEQ*HDIM];
__device__ __half g_Vh[(size_t)BATCH*NHEADS*SEQ*HDIM];
__device__ __half g_Ah[(size_t)BATCH*SEQ*DMODEL];
__device__ __half g_Xh[(size_t)MROWS*DMODEL];
__device__ __half g_Wth[4u*1024u*1024u];     // 4 transposed weights [N,K] fp16

__device__ __forceinline__ uint32_t smem_u32(const void* p) {
    uint32_t a;
    asm("{ .reg .u64 t; cvta.to.shared.u64 t, %1; cvt.u32.u64 %0, t; }"
        : "=r"(a) : "l"(p));
    return a;
}
__device__ __forceinline__ void mma_f16(float* c, const uint32_t* a, const uint32_t* b) {
    asm volatile(
        "mma.sync.aligned.m16n8k16.row.col.f32.f16.f16.f32 "
        "{%0,%1,%2,%3}, {%4,%5,%6,%7}, {%8,%9}, {%0,%1,%2,%3};"
        : "+f"(c[0]), "+f"(c[1]), "+f"(c[2]), "+f"(c[3])
        : "r"(a[0]), "r"(a[1]), "r"(a[2]), "r"(a[3]), "r"(b[0]), "r"(b[1]));
}
__device__ __forceinline__ uint32_t pack_h2(float x, float y) {
    __half2 h = __floats2half2_rn(x, y);
    return *(uint32_t*)&h;
}
__device__ __forceinline__ float fexp2(float x) {
    float r;
    asm("ex2.approx.f32 %0, %1;" : "=f"(r) : "f"(x));
    return r;
}
#define LDSM_X4(r0, r1, r2, r3, addr) \
    asm volatile("ldmatrix.sync.aligned.m8n8.x4.shared.b16 {%0,%1,%2,%3}, [%4];" \
        : "=r"(r0), "=r"(r1), "=r"(r2), "=r"(r3) : "r"(addr))
#define LDSM_X4_T(r0, r1, r2, r3, addr) \
    asm volatile("ldmatrix.sync.aligned.m8n8.x4.trans.shared.b16 {%0,%1,%2,%3}, [%4];" \
        : "=r"(r0), "=r"(r1), "=r"(r2), "=r"(r3) : "r"(addr))
#define CP_ASYNC16(dst, src) \
    asm volatile("cp.async.cg.shared.global [%0], [%1], 16;" :: "r"(dst), "l"(src))
#define CP_COMMIT() asm volatile("cp.async.commit_group;" ::: "memory")
#define CP_WAIT1()  asm volatile("cp.async.wait_group 1;"  ::: "memory")
#define CP_WAIT0()  asm volatile("cp.async.wait_group 0;"  ::: "memory")

// ---------------------------------------------------------------------------
// Convert x to fp16. 8 floats -> 8 halves per thread.
// ---------------------------------------------------------------------------
__global__ __launch_bounds__(256)
void tohalf_kernel(const float4* __restrict__ in, uint4* __restrict__ out)
{
    const int i = blockIdx.x * 256 + threadIdx.x;
    float4 v0 = in[2 * i], v1 = in[2 * i + 1];
    uint4 o;
    o.x = pack_h2(v0.x, v0.y); o.y = pack_h2(v0.z, v0.w);
    o.z = pack_h2(v1.x, v1.y); o.w = pack_h2(v1.z, v1.w);
    out[i] = o;
}

// ---------------------------------------------------------------------------
// Fused transpose+halve of all 4 weights: z selects source.
// ---------------------------------------------------------------------------
__global__ __launch_bounds__(256)
void transpose4_kernel(const float* __restrict__ W0, const float* __restrict__ W1,
                       const float* __restrict__ W2, const float* __restrict__ W3,
                       __half* __restrict__ WtBase)
{
    __shared__ float t[32][33];
    const int z = blockIdx.z;
    const float* W = (z == 0) ? W0 : (z == 1) ? W1 : (z == 2) ? W2 : W3;
    __half* Wt = WtBase + (size_t)z * 1024u * 1024u;
    const int x0 = blockIdx.x * 32, y0 = blockIdx.y * 32;
    const int tx = threadIdx.x, ty = threadIdx.y;
    #pragma unroll
    for (int i = 0; i < 32; i += 8)
        t[ty + i][tx] = W[(size_t)(y0 + ty + i) * 1024 + x0 + tx];
    __syncthreads();
    #pragma unroll
    for (int i = 0; i < 32; i += 8)
        Wt[(size_t)(x0 + ty + i) * 1024 + y0 + tx] = __float2half_rn(t[tx][ty + i]);
}

// ---------------------------------------------------------------------------
// Pipelined fp16 GEMM (cp.async 3-stage, 1 barrier/iter, ldmatrix frags):
// Y = X @ W + bias. CTA 128x128x32, 256 thr, warp 64x32 of m16n8k16.
// Stride 40 halves. OUT_HEADED=1 && z==0 output folds QSCALE.
// ---------------------------------------------------------------------------
#define GSTH (128*40)                 // halves per tile per stage
#define GP_SMEM (6*GSTH*2)            // 61440 B: 3 stages x (As+Bs)

template<int OUT_HEADED>
__global__ __launch_bounds__(256, 2)
void gemm_pipe(const __half* __restrict__ X, const __half* __restrict__ WtBase,
               const float* b0, const float* b1, const float* b2,
               void* y0, void* y1, void* y2)
{
    extern __shared__ __half smh[];
    __half* As = smh;              // [3][128][40]
    __half* Bs = smh + 3 * GSTH;   // [3][128][40]

    const int z = blockIdx.z;
    const __half* Bt   = WtBase + (size_t)z * 1024u * 1024u;
    const float*  bias = (z == 0) ? b0 : (z == 1) ? b1 : b2;
    void*         Yv   = (z == 0) ? y0 : (z == 1) ? y1 : y2;

    const int tid = threadIdx.x;
    const int wid = tid >> 5, lane = tid & 31;
    const int bn = blockIdx.x, bm = blockIdx.y;
    const int warp_m = wid >> 2, warp_n = wid & 3;
    const int g = lane >> 2, tig = lane & 3;
    const int m0 = warp_m * 64, n0 = warp_n * 32;

    const __half* Xb  = X  + (size_t)(bm * 128) * DMODEL;
    const __half* Btb = Bt + (size_t)(bn * 128) * DMODEL;

    const uint32_t As_u = smem_u32(As), Bs_u = smem_u32(Bs);
    const uint32_t a_base = As_u + ((m0 + (lane & 15)) * 40 + (lane >> 4) * 8) * 2;
    const uint32_t b_base0 = Bs_u +
        ((n0 + 0  + ((lane >> 4) & 1) * 8 + (lane & 7)) * 40 + ((lane >> 3) & 1) * 8) * 2;
    const uint32_t b_base1 = Bs_u +
        ((n0 + 16 + ((lane >> 4) & 1) * 8 + (lane & 7)) * 40 + ((lane >> 3) & 1) * 8) * 2;

    #define ISSUE(stage, chunk) do { \
        const int _k0 = (chunk) * 32; \
        _Pragma("unroll") \
        for (int _j = 0; _j < 2; _j++) { \
            const int _c = tid + _j * 256; \
            const int _r = _c >> 2, _o = (_c & 3) * 8; \
            CP_ASYNC16(As_u + ((stage) * GSTH + _r * 40 + _o) * 2, \
                       Xb  + (size_t)_r * DMODEL + _k0 + _o); \
            CP_ASYNC16(Bs_u + ((stage) * GSTH + _r * 40 + _o) * 2, \
                       Btb + (size_t)_r * DMODEL + _k0 + _o); \
        } \
        CP_COMMIT(); \
    } while (0)

    float c[4][4][4];
    #pragma unroll
    for (int mf = 0; mf < 4; mf++)
        #pragma unroll
        for (int nf = 0; nf < 4; nf++)
            #pragma unroll
            for (int i = 0; i < 4; i++) c[mf][nf][i] = 0.f;

    ISSUE(0, 0);
    ISSUE(1, 1);

    for (int ch = 0; ch < 32; ch++) {
        if (ch + 1 < 32) { CP_WAIT1(); } else { CP_WAIT0(); }
        __syncthreads();
        if (ch + 2 < 32) ISSUE((ch + 2) % 3, ch + 2);

        const uint32_t soff = (uint32_t)((ch % 3) * GSTH) * 2;
        #pragma unroll
        for (int kk = 0; kk < 32; kk += 16) {
            uint32_t a[4][4], b[4][2];
            #pragma unroll
            for (int mf = 0; mf < 4; mf++)
                LDSM_X4(a[mf][0], a[mf][1], a[mf][2], a[mf][3],
                        a_base + soff + kk * 2 + mf * (16 * 40 * 2));
            LDSM_X4(b[0][0], b[0][1], b[1][0], b[1][1], b_base0 + soff + kk * 2);
            LDSM_X4(b[2][0], b[2][1], b[3][0], b[3][1], b_base1 + soff + kk * 2);
            #pragma unroll
            for (int mf = 0; mf < 4; mf++)
                #pragma unroll
                for (int nf = 0; nf < 4; nf++)
                    mma_f16(c[mf][nf], a[mf], b[nf]);
        }
    }

    const float osc = (OUT_HEADED && z == 0) ? QSCALE : 1.0f;
    #pragma unroll
    for (int mf = 0; mf < 4; mf++) {
        #pragma unroll
        for (int nf = 0; nf < 4; nf++) {
            const int col = bn * 128 + n0 + nf * 8 + 2 * tig;
            const float bz0 = bias[col], bz1 = bias[col + 1];
            #pragma unroll
            for (int half_ = 0; half_ < 2; half_++) {
                const int m = bm * 128 + m0 + mf * 16 + g + half_ * 8;
                const float vx = (c[mf][nf][half_ * 2 + 0] + bz0) * osc;
                const float vy = (c[mf][nf][half_ * 2 + 1] + bz1) * osc;
                if (OUT_HEADED) {
                    const int bb = m >> 11, t = m & 2047;
                    const int h = col >> 6, d = col & 63;
                    __half* Y = (__half*)Yv;
                    *(uint32_t*)&Y[(((size_t)(bb * NHEADS + h) * SEQ) + t) * HDIM + d] =
                        pack_h2(vx, vy);
                } else {
                    float* Y = (float*)Yv;
                    float2 v = { vx, vy };
                    *(float2*)&Y[(size_t)m * DMODEL + col] = v;
                }
            }
        }
    }
    #undef ISSUE
}

// ---------------------------------------------------------------------------
// fp16 flash attention: cp.async 3-stage K/V (1 barrier/tile), ldmatrix frags,
// V via .trans, Q pre-scaled by QSCALE so softmax runs in exp2 domain.
// Grid (16, 64), 256 thr = 8 warps; warp owns 16 q-rows. KV tile 64.
// Ps [128][72] warp-private; Ks/Vs [3][64][72].
// ---------------------------------------------------------------------------
#define FPS 72
#define KVSZ (64*FPS)
#define FLASH_SMEM ((128*FPS + 6*KVSZ) * 2)   // 73728 B

__global__ __launch_bounds__(256, 2)
void flash_mma()
{
    extern __shared__ __half smh[];
    __half* Ps = smh;                    // [128][72] Q staging, then P
    __half* Ks = smh + 128 * FPS;        // [3][64][72] K rows [n][k]
    __half* Vs = Ks + 3 * KVSZ;          // [3][64][72] V rows [t][d]

    const int tid = threadIdx.x;
    const int wid = tid >> 5, lane = tid & 31;
    const int g = lane >> 2, tig = lane & 3;
    const int qb = (int)(gridDim.x - 1) - (int)blockIdx.x;   // heavy blocks first
    const int bh = blockIdx.y;
    const int m0 = wid * 16;
    const int r0 = m0 + g, r1 = m0 + g + 8;
    const int qg0 = qb * 128 + r0, qg1 = qb * 128 + r1;

    const uint32_t Ps_u = smem_u32(Ps), Ks_u = smem_u32(Ks), Vs_u = smem_u32(Vs);
    const uint32_t pa_base = Ps_u + ((m0 + (lane & 15)) * FPS + (lane >> 4) * 8) * 2;
    const uint32_t kb_row = ((lane >> 4) & 1) * 8 + (lane & 7);
    const uint32_t kb_koff = ((lane >> 3) & 1) * 8;
    const uint32_t vt_row = ((lane >> 3) & 1) * 8 + (lane & 7);
    const uint32_t vt_col = (lane >> 4) * 8;

    const __half* Kb = g_Kh + (size_t)bh * SEQ * HDIM;
    const __half* Vb = g_Vh + (size_t)bh * SEQ * HDIM;

    #define ISSUE_KV(stage, kt_) do { \
        const __half* _ks = Kb + (size_t)(kt_) * 64 * HDIM; \
        const __half* _vs = Vb + (size_t)(kt_) * 64 * HDIM; \
        _Pragma("unroll") \
        for (int _j = 0; _j < 2; _j++) { \
            const int _c = tid + _j * 256; \
            const int _r = _c >> 3, _o = (_c & 7) * 8; \
            CP_ASYNC16(Ks_u + ((stage) * KVSZ + _r * FPS + _o) * 2, _ks + _r * HDIM + _o); \
            CP_ASYNC16(Vs_u + ((stage) * KVSZ + _r * FPS + _o) * 2, _vs + _r * HDIM + _o); \
        } \
        CP_COMMIT(); \
    } while (0)

    // Stage Q tile (plain loads, once)
    {
        const __half* Qb = g_Qh + ((size_t)bh * SEQ + qb * 128) * HDIM;
        #pragma unroll
        for (int j = 0; j < 4; j++) {
            const int c = tid + j * 256;
            const int r = c >> 3, o = (c & 7) * 8;
            *(uint4*)(Ps + r * FPS + o) = *(const uint4*)(Qb + (size_t)r * HDIM + o);
        }
    }
    const int ktiles = (qb + 1) * 2;
    ISSUE_KV(0, 0);
    ISSUE_KV(1, 1);
    __syncthreads();

    // Q fragments (4 k-steps of 16), register-resident
    uint32_t qa[4][4];
    #pragma unroll
    for (int kf = 0; kf < 4; kf++)
        LDSM_X4(qa[kf][0], qa[kf][1], qa[kf][2], qa[kf][3], pa_base + kf * 16 * 2);

    float o[8][4];
    #pragma unroll
    for (int nf = 0; nf < 8; nf++)
        #pragma unroll
        for (int i = 0; i < 4; i++) o[nf][i] = 0.f;
    float mr0 = -INFINITY, mr1 = -INFINITY, l0 = 0.f, l1 = 0.f;

    for (int kt = 0; kt < ktiles; kt++) {
        if (kt + 1 < ktiles) { CP_WAIT1(); } else { CP_WAIT0(); }
        __syncthreads();
        if (kt + 2 < ktiles) ISSUE_KV((kt + 2) % 3, kt + 2);

        const uint32_t ksoff = (uint32_t)((kt % 3) * KVSZ) * 2;

        // S = Q @ K^T (scores already in exp2 domain via QSCALE)
        float sacc[8][4];
        #pragma unroll
        for (int nf = 0; nf < 8; nf++)
            #pragma unroll
            for (int i = 0; i < 4; i++) sacc[nf][i] = 0.f;

        #pragma unroll
        for (int kf = 0; kf < 4; kf++) {
            #pragma unroll
            for (int p = 0; p < 4; p++) {
                uint32_t b[2][2];
                LDSM_X4(b[0][0], b[0][1], b[1][0], b[1][1],
                        Ks_u + ksoff + ((p * 16 + kb_row) * FPS + kf * 16 + kb_koff) * 2);
                mma_f16(sacc[2 * p],     qa[kf], b[0]);
                mma_f16(sacc[2 * p + 1], qa[kf], b[1]);
            }
        }

        const bool diag = (kt >= 2 * qb);
        if (diag) {
            #pragma unroll
            for (int nf = 0; nf < 8; nf++) {
                const int cb = kt * 64 + nf * 8 + 2 * tig;
                if (cb     > qg0) sacc[nf][0] = -INFINITY;
                if (cb + 1 > qg0) sacc[nf][1] = -INFINITY;
                if (cb     > qg1) sacc[nf][2] = -INFINITY;
                if (cb + 1 > qg1) sacc[nf][3] = -INFINITY;
            }
        }

        float mn0 = sacc[0][0], mn1 = sacc[0][2];
        #pragma unroll
        for (int nf = 0; nf < 8; nf++) {
            mn0 = fmaxf(mn0, fmaxf(sacc[nf][0], sacc[nf][1]));
            mn1 = fmaxf(mn1, fmaxf(sacc[nf][2], sacc[nf][3]));
        }
        mn0 = fmaxf(mn0, __shfl_xor_sync(0xffffffffu, mn0, 1));
        mn0 = fmaxf(mn0, __shfl_xor_sync(0xffffffffu, mn0, 2));
        mn1 = fmaxf(mn1, __shfl_xor_sync(0xffffffffu, mn1, 1));
        mn1 = fmaxf(mn1, __shfl_xor_sync(0xffffffffu, mn1, 2));
        mn0 = fmaxf(mr0, mn0);
        mn1 = fmaxf(mr1, mn1);

        const float cr0 = fexp2(mr0 - mn0);
        const float cr1 = fexp2(mr1 - mn1);
        mr0 = mn0; mr1 = mn1;
        #pragma unroll
        for (int nf = 0; nf < 8; nf++) {
            o[nf][0] *= cr0; o[nf][1] *= cr0;
            o[nf][2] *= cr1; o[nf][3] *= cr1;
        }

        float ps0 = 0.f, ps1 = 0.f;
        #pragma unroll
        for (int nf = 0; nf < 8; nf++) {
            const float p0 = fexp2(sacc[nf][0] - mn0);
            const float p1 = fexp2(sacc[nf][1] - mn0);
            const float p2 = fexp2(sacc[nf][2] - mn1);
            const float p3 = fexp2(sacc[nf][3] - mn1);
            ps0 += p0 + p1; ps1 += p2 + p3;
            *(uint32_t*)&Ps[r0 * FPS + nf * 8 + 2 * tig] = pack_h2(p0, p1);
            *(uint32_t*)&Ps[r1 * FPS + nf * 8 + 2 * tig] = pack_h2(p2, p3);
        }
        ps0 += __shfl_xor_sync(0xffffffffu, ps0, 1);
        ps0 += __shfl_xor_sync(0xffffffffu, ps0, 2);
        ps1 += __shfl_xor_sync(0xffffffffu, ps1, 1);
        ps1 += __shfl_xor_sync(0xffffffffu, ps1, 2);
        l0 = l0 * cr0 + ps0;
        l1 = l1 * cr1 + ps1;
        __syncwarp();

        // O += P @ V  (P warp-private rows; V [t][d] via ldmatrix.trans)
        #pragma unroll
        for (int kf = 0; kf < 4; kf++) {
            uint32_t pa[4];
            LDSM_X4(pa[0], pa[1], pa[2], pa[3], pa_base + kf * 16 * 2);
            #pragma unroll
            for (int p = 0; p < 4; p++) {
                uint32_t b[2][2];
                LDSM_X4_T(b[0][0], b[0][1], b[1][0], b[1][1],
                          Vs_u + ksoff + ((kf * 16 + vt_row) * FPS + p * 16 + vt_col) * 2);
                mma_f16(o[2 * p],     pa, b[0]);
                mma_f16(o[2 * p + 1], pa, b[1]);
            }
        }
    }

    // Epilogue: normalize, write half to g_Ah [b, t, h*64+d]
    const float i0 = 1.f / l0, i1 = 1.f / l1;
    const int bb = bh >> 4, h = bh & 15;
    __half* A0 = g_Ah + ((size_t)(bb * SEQ) + qg0) * DMODEL + h * HDIM;
    __half* A1 = g_Ah + ((size_t)(bb * SEQ) + qg1) * DMODEL + h * HDIM;
    #pragma unroll
    for (int nf = 0; nf < 8; nf++) {
        *(uint32_t*)(A0 + nf * 8 + 2 * tig) = pack_h2(o[nf][0] * i0, o[nf][1] * i0);
        *(uint32_t*)(A1 + nf * 8 + 2 * tig) = pack_h2(o[nf][2] * i1, o[nf][3] * i1);
    }
    #undef ISSUE_KV
}

// ---------------------------------------------------------------------------
extern "C" void kernel_launch(void* const* d_in, const int* in_sizes, int n_in,
                              void* d_out, int out_size)
{
    const float* x  = (const float*)d_in[0];
    const float* Wq = (const float*)d_in[2];
    const float* bq = (const float*)d_in[3];
    const float* Wk = (const float*)d_in[4];
    const float* bk = (const float*)d_in[5];
    const float* Wv = (const float*)d_in[6];
    const float* bv = (const float*)d_in[7];
    const float* Wo = (const float*)d_in[8];
    const float* bo = (const float*)d_in[9];
    float* out = (float*)d_out;

    __half *Qp, *Kp, *Vp, *Ap, *Wt, *Xh;
    cudaGetSymbolAddress((void**)&Qp, g_Qh);
    cudaGetSymbolAddress((void**)&Kp, g_Kh);
    cudaGetSymbolAddress((void**)&Vp, g_Vh);
    cudaGetSymbolAddress((void**)&Ap, g_Ah);
    cudaGetSymbolAddress((void**)&Wt, g_Wth);
    cudaGetSymbolAddress((void**)&Xh, g_Xh);

    cudaFuncSetAttribute(flash_mma, cudaFuncAttributeMaxDynamicSharedMemorySize,
                         FLASH_SMEM);
    cudaFuncSetAttribute(gemm_pipe<1>, cudaFuncAttributeMaxDynamicSharedMemorySize,
                         GP_SMEM);
    cudaFuncSetAttribute(gemm_pipe<0>, cudaFuncAttributeMaxDynamicSharedMemorySize,
                         GP_SMEM);

    tohalf_kernel<<<(MROWS * DMODEL) / (256 * 8), 256>>>((const float4*)x, (uint4*)Xh);
    dim3 tgrid(32, 32, 4), tblk(32, 8);
    transpose4_kernel<<<tgrid, tblk>>>(Wq, Wk, Wv, Wo, Wt);

    // Fused QKV projection (z selects weight/bias/output; Q pre-scaled)
    dim3 qkvgrid(DMODEL / 128, MROWS / 128, 3);   // (8, 64, 3)
    gemm_pipe<1><<<qkvgrid, 256, GP_SMEM>>>(Xh, Wt, bq, bk, bv, Qp, Kp, Vp);

    dim3 fgrid(SEQ / 128, BATCH * NHEADS);        // (16, 64)
    flash_mma<<<fgrid, 256, FLASH_SMEM>>>();

    dim3 ogrid(DMODEL / 128, MROWS / 128, 1);
    gemm_pipe<0><<<ogrid, 256, GP_SMEM>>>(Ap, Wt + 3u * 1024u * 1024u,
                                          bo, bo, bo, out, out, out);
}

// round 17
// speedup vs baseline: 9.5898x; 1.0808x over previous
#include <cuda_runtime.h>
#include <cuda_fp16.h>
#include <math.h>
#include <stdint.h>

#define BATCH 4
#define SEQ   2048
#define DMODEL 1024
#define NHEADS 16
#define HDIM  64
#define MROWS (BATCH*SEQ)   // 8192

// 1/sqrt(64) * log2(e), folded into Q at projection time
#define QSCALE 0.18033688011112042f

// Scratch (no cudaMalloc allowed) — all fp16
__device__ __half g_Qh[(size_t)BATCH*NHEADS*SEQ*HDIM];
__device__ __half g_Kh[(size_t)BATCH*NHEADS*SEQ*HDIM];
__device__ __half g_Vh[(size_t)BATCH*NHEADS*SEQ*HDIM];
__device__ __half g_Ah[(size_t)BATCH*SEQ*DMODEL];
__device__ __half g_Xh[(size_t)MROWS*DMODEL];
__device__ __half g_Wth[4u*1024u*1024u];     // 4 transposed weights [N,K] fp16

__device__ __forceinline__ uint32_t smem_u32(const void* p) {
    uint32_t a;
    asm("{ .reg .u64 t; cvta.to.shared.u64 t, %1; cvt.u32.u64 %0, t; }"
        : "=r"(a) : "l"(p));
    return a;
}
__device__ __forceinline__ void mma_f16(float* c, const uint32_t* a, const uint32_t* b) {
    asm volatile(
        "mma.sync.aligned.m16n8k16.row.col.f32.f16.f16.f32 "
        "{%0,%1,%2,%3}, {%4,%5,%6,%7}, {%8,%9}, {%0,%1,%2,%3};"
        : "+f"(c[0]), "+f"(c[1]), "+f"(c[2]), "+f"(c[3])
        : "r"(a[0]), "r"(a[1]), "r"(a[2]), "r"(a[3]), "r"(b[0]), "r"(b[1]));
}
__device__ __forceinline__ uint32_t pack_h2(float x, float y) {
    __half2 h = __floats2half2_rn(x, y);
    return *(uint32_t*)&h;
}
__device__ __forceinline__ float fexp2(float x) {
    float r;
    asm("ex2.approx.f32 %0, %1;" : "=f"(r) : "f"(x));
    return r;
}
__device__ __forceinline__ uint32_t ex2_h2(uint32_t x) {
    uint32_t r;
    asm("ex2.approx.f16x2 %0, %1;" : "=r"(r) : "r"(x));
    return r;
}
#define LDSM_X4(r0, r1, r2, r3, addr) \
    asm volatile("ldmatrix.sync.aligned.m8n8.x4.shared.b16 {%0,%1,%2,%3}, [%4];" \
        : "=r"(r0), "=r"(r1), "=r"(r2), "=r"(r3) : "r"(addr))
#define LDSM_X4_T(r0, r1, r2, r3, addr) \
    asm volatile("ldmatrix.sync.aligned.m8n8.x4.trans.shared.b16 {%0,%1,%2,%3}, [%4];" \
        : "=r"(r0), "=r"(r1), "=r"(r2), "=r"(r3) : "r"(addr))
#define CP_ASYNC16(dst, src) \
    asm volatile("cp.async.cg.shared.global [%0], [%1], 16;" :: "r"(dst), "l"(src))
#define CP_COMMIT() asm volatile("cp.async.commit_group;" ::: "memory")
#define CP_WAIT1()  asm volatile("cp.async.wait_group 1;"  ::: "memory")
#define CP_WAIT0()  asm volatile("cp.async.wait_group 0;"  ::: "memory")

// ---------------------------------------------------------------------------
// Convert x to fp16. 8 floats -> 8 halves per thread.
// ---------------------------------------------------------------------------
__global__ __launch_bounds__(256)
void tohalf_kernel(const float4* __restrict__ in, uint4* __restrict__ out)
{
    const int i = blockIdx.x * 256 + threadIdx.x;
    float4 v0 = in[2 * i], v1 = in[2 * i + 1];
    uint4 o;
    o.x = pack_h2(v0.x, v0.y); o.y = pack_h2(v0.z, v0.w);
    o.z = pack_h2(v1.x, v1.y); o.w = pack_h2(v1.z, v1.w);
    out[i] = o;
}

// ---------------------------------------------------------------------------
// Fused transpose+halve of all 4 weights: z selects source.
// ---------------------------------------------------------------------------
__global__ __launch_bounds__(256)
void transpose4_kernel(const float* __restrict__ W0, const float* __restrict__ W1,
                       const float* __restrict__ W2, const float* __restrict__ W3,
                       __half* __restrict__ WtBase)
{
    __shared__ float t[32][33];
    const int z = blockIdx.z;
    const float* W = (z == 0) ? W0 : (z == 1) ? W1 : (z == 2) ? W2 : W3;
    __half* Wt = WtBase + (size_t)z * 1024u * 1024u;
    const int x0 = blockIdx.x * 32, y0 = blockIdx.y * 32;
    const int tx = threadIdx.x, ty = threadIdx.y;
    #pragma unroll
    for (int i = 0; i < 32; i += 8)
        t[ty + i][tx] = W[(size_t)(y0 + ty + i) * 1024 + x0 + tx];
    __syncthreads();
    #pragma unroll
    for (int i = 0; i < 32; i += 8)
        Wt[(size_t)(x0 + ty + i) * 1024 + y0 + tx] = __float2half_rn(t[tx][ty + i]);
}

// ---------------------------------------------------------------------------
// Pipelined fp16 GEMM (cp.async 3-stage, 1 barrier/iter, ldmatrix frags):
// Y = X @ W + bias. CTA 128x128x32, 256 thr, warp 64x32 of m16n8k16.
// Stride 40 halves. OUT_HEADED=1 && z==0 output folds QSCALE.
// ---------------------------------------------------------------------------
#define GSTH (128*40)                 // halves per tile per stage
#define GP_SMEM (6*GSTH*2)            // 61440 B: 3 stages x (As+Bs)

template<int OUT_HEADED>
__global__ __launch_bounds__(256, 2)
void gemm_pipe(const __half* __restrict__ X, const __half* __restrict__ WtBase,
               const float* b0, const float* b1, const float* b2,
               void* y0, void* y1, void* y2)
{
    extern __shared__ __half smh[];
    __half* As = smh;              // [3][128][40]
    __half* Bs = smh + 3 * GSTH;   // [3][128][40]

    const int z = blockIdx.z;
    const __half* Bt   = WtBase + (size_t)z * 1024u * 1024u;
    const float*  bias = (z == 0) ? b0 : (z == 1) ? b1 : b2;
    void*         Yv   = (z == 0) ? y0 : (z == 1) ? y1 : y2;

    const int tid = threadIdx.x;
    const int wid = tid >> 5, lane = tid & 31;
    const int bn = blockIdx.x, bm = blockIdx.y;
    const int warp_m = wid >> 2, warp_n = wid & 3;
    const int g = lane >> 2, tig = lane & 3;
    const int m0 = warp_m * 64, n0 = warp_n * 32;

    const __half* Xb  = X  + (size_t)(bm * 128) * DMODEL;
    const __half* Btb = Bt + (size_t)(bn * 128) * DMODEL;

    const uint32_t As_u = smem_u32(As), Bs_u = smem_u32(Bs);
    const uint32_t a_base = As_u + ((m0 + (lane & 15)) * 40 + (lane >> 4) * 8) * 2;
    const uint32_t b_base0 = Bs_u +
        ((n0 + 0  + ((lane >> 4) & 1) * 8 + (lane & 7)) * 40 + ((lane >> 3) & 1) * 8) * 2;
    const uint32_t b_base1 = Bs_u +
        ((n0 + 16 + ((lane >> 4) & 1) * 8 + (lane & 7)) * 40 + ((lane >> 3) & 1) * 8) * 2;

    #define ISSUE(stage, chunk) do { \
        const int _k0 = (chunk) * 32; \
        _Pragma("unroll") \
        for (int _j = 0; _j < 2; _j++) { \
            const int _c = tid + _j * 256; \
            const int _r = _c >> 2, _o = (_c & 3) * 8; \
            CP_ASYNC16(As_u + ((stage) * GSTH + _r * 40 + _o) * 2, \
                       Xb  + (size_t)_r * DMODEL + _k0 + _o); \
            CP_ASYNC16(Bs_u + ((stage) * GSTH + _r * 40 + _o) * 2, \
                       Btb + (size_t)_r * DMODEL + _k0 + _o); \
        } \
        CP_COMMIT(); \
    } while (0)

    float c[4][4][4];
    #pragma unroll
    for (int mf = 0; mf < 4; mf++)
        #pragma unroll
        for (int nf = 0; nf < 4; nf++)
            #pragma unroll
            for (int i = 0; i < 4; i++) c[mf][nf][i] = 0.f;

    ISSUE(0, 0);
    ISSUE(1, 1);

    for (int ch = 0; ch < 32; ch++) {
        if (ch + 1 < 32) { CP_WAIT1(); } else { CP_WAIT0(); }
        __syncthreads();
        if (ch + 2 < 32) ISSUE((ch + 2) % 3, ch + 2);

        const uint32_t soff = (uint32_t)((ch % 3) * GSTH) * 2;
        #pragma unroll
        for (int kk = 0; kk < 32; kk += 16) {
            uint32_t a[4][4], b[4][2];
            #pragma unroll
            for (int mf = 0; mf < 4; mf++)
                LDSM_X4(a[mf][0], a[mf][1], a[mf][2], a[mf][3],
                        a_base + soff + kk * 2 + mf * (16 * 40 * 2));
            LDSM_X4(b[0][0], b[0][1], b[1][0], b[1][1], b_base0 + soff + kk * 2);
            LDSM_X4(b[2][0], b[2][1], b[3][0], b[3][1], b_base1 + soff + kk * 2);
            #pragma unroll
            for (int mf = 0; mf < 4; mf++)
                #pragma unroll
                for (int nf = 0; nf < 4; nf++)
                    mma_f16(c[mf][nf], a[mf], b[nf]);
        }
    }

    const float osc = (OUT_HEADED && z == 0) ? QSCALE : 1.0f;
    #pragma unroll
    for (int mf = 0; mf < 4; mf++) {
        #pragma unroll
        for (int nf = 0; nf < 4; nf++) {
            const int col = bn * 128 + n0 + nf * 8 + 2 * tig;
            const float bz0 = bias[col], bz1 = bias[col + 1];
            #pragma unroll
            for (int half_ = 0; half_ < 2; half_++) {
                const int m = bm * 128 + m0 + mf * 16 + g + half_ * 8;
                const float vx = (c[mf][nf][half_ * 2 + 0] + bz0) * osc;
                const float vy = (c[mf][nf][half_ * 2 + 1] + bz1) * osc;
                if (OUT_HEADED) {
                    const int bb = m >> 11, t = m & 2047;
                    const int h = col >> 6, d = col & 63;
                    __half* Y = (__half*)Yv;
                    *(uint32_t*)&Y[(((size_t)(bb * NHEADS + h) * SEQ) + t) * HDIM + d] =
                        pack_h2(vx, vy);
                } else {
                    float* Y = (float*)Yv;
                    float2 v = { vx, vy };
                    *(float2*)&Y[(size_t)m * DMODEL + col] = v;
                }
            }
        }
    }
    #undef ISSUE
}

// ---------------------------------------------------------------------------
// fp16 flash attention: cp.async 3-stage K/V, register-resident P (C-frag of
// S == A-frag of PV), ex2.approx.f16x2 softmax, row-sum l via ones-MMA.
// Grid (16, 64), 256 thr = 8 warps; warp owns 16 q-rows. KV tile 64.
// Qs [128][72]; Ks/Vs [3][64][72]. Stride 72 halves, conflict-free.
// ---------------------------------------------------------------------------
#define FPS 72
#define KVSZ (64*FPS)
#define FLASH_SMEM ((128*FPS + 6*KVSZ) * 2)   // 73728 B

__global__ __launch_bounds__(256, 2)
void flash_mma()
{
    extern __shared__ __half smh[];
    __half* Qs = smh;                    // [128][72] Q staging
    __half* Ks = smh + 128 * FPS;        // [3][64][72] K rows [n][k]
    __half* Vs = Ks + 3 * KVSZ;          // [3][64][72] V rows [t][d]

    const int tid = threadIdx.x;
    const int wid = tid >> 5, lane = tid & 31;
    const int g = lane >> 2, tig = lane & 3;
    const int qb = (int)(gridDim.x - 1) - (int)blockIdx.x;   // heavy blocks first
    const int bh = blockIdx.y;
    const int m0 = wid * 16;
    const int r0 = m0 + g, r1 = m0 + g + 8;
    const int qg0 = qb * 128 + r0, qg1 = qb * 128 + r1;

    const uint32_t Qs_u = smem_u32(Qs), Ks_u = smem_u32(Ks), Vs_u = smem_u32(Vs);
    const uint32_t qa_base = Qs_u + ((m0 + (lane & 15)) * FPS + (lane >> 4) * 8) * 2;
    const uint32_t kb_row = ((lane >> 4) & 1) * 8 + (lane & 7);
    const uint32_t kb_koff = ((lane >> 3) & 1) * 8;
    const uint32_t vt_row = ((lane >> 3) & 1) * 8 + (lane & 7);
    const uint32_t vt_col = (lane >> 4) * 8;

    const __half* Kb = g_Kh + (size_t)bh * SEQ * HDIM;
    const __half* Vb = g_Vh + (size_t)bh * SEQ * HDIM;

    #define ISSUE_KV(stage, kt_) do { \
        const __half* _ks = Kb + (size_t)(kt_) * 64 * HDIM; \
        const __half* _vs = Vb + (size_t)(kt_) * 64 * HDIM; \
        _Pragma("unroll") \
        for (int _j = 0; _j < 2; _j++) { \
            const int _c = tid + _j * 256; \
            const int _r = _c >> 3, _o = (_c & 7) * 8; \
            CP_ASYNC16(Ks_u + ((stage) * KVSZ + _r * FPS + _o) * 2, _ks + _r * HDIM + _o); \
            CP_ASYNC16(Vs_u + ((stage) * KVSZ + _r * FPS + _o) * 2, _vs + _r * HDIM + _o); \
        } \
        CP_COMMIT(); \
    } while (0)

    // Stage Q tile
    {
        const __half* Qb = g_Qh + ((size_t)bh * SEQ + qb * 128) * HDIM;
        #pragma unroll
        for (int j = 0; j < 4; j++) {
            const int c = tid + j * 256;
            const int r = c >> 3, o = (c & 7) * 8;
            *(uint4*)(Qs + r * FPS + o) = *(const uint4*)(Qb + (size_t)r * HDIM + o);
        }
    }
    const int ktiles = (qb + 1) * 2;
    ISSUE_KV(0, 0);
    ISSUE_KV(1, 1);
    __syncthreads();

    // Q fragments (4 k-steps of 16), register-resident
    uint32_t qa[4][4];
    #pragma unroll
    for (int kf = 0; kf < 4; kf++)
        LDSM_X4(qa[kf][0], qa[kf][1], qa[kf][2], qa[kf][3], qa_base + kf * 16 * 2);

    float o[8][4];
    #pragma unroll
    for (int nf = 0; nf < 8; nf++)
        #pragma unroll
        for (int i = 0; i < 4; i++) o[nf][i] = 0.f;
    float ol[4] = {0.f, 0.f, 0.f, 0.f};          // row-sum accumulator (l)
    float mr0 = -INFINITY, mr1 = -INFINITY;
    const uint32_t ONES[2] = {0x3C003C00u, 0x3C003C00u};

    for (int kt = 0; kt < ktiles; kt++) {
        if (kt + 1 < ktiles) { CP_WAIT1(); } else { CP_WAIT0(); }
        __syncthreads();
        if (kt + 2 < ktiles) ISSUE_KV((kt + 2) % 3, kt + 2);

        const uint32_t ksoff = (uint32_t)((kt % 3) * KVSZ) * 2;

        // S = Q @ K^T (scores already in exp2 domain via QSCALE)
        float sacc[8][4];
        #pragma unroll
        for (int nf = 0; nf < 8; nf++)
            #pragma unroll
            for (int i = 0; i < 4; i++) sacc[nf][i] = 0.f;

        #pragma unroll
        for (int kf = 0; kf < 4; kf++) {
            #pragma unroll
            for (int p = 0; p < 4; p++) {
                uint32_t b[2][2];
                LDSM_X4(b[0][0], b[0][1], b[1][0], b[1][1],
                        Ks_u + ksoff + ((p * 16 + kb_row) * FPS + kf * 16 + kb_koff) * 2);
                mma_f16(sacc[2 * p],     qa[kf], b[0]);
                mma_f16(sacc[2 * p + 1], qa[kf], b[1]);
            }
        }

        const bool diag = (kt >= 2 * qb);
        if (diag) {
            #pragma unroll
            for (int nf = 0; nf < 8; nf++) {
                const int cb = kt * 64 + nf * 8 + 2 * tig;
                if (cb     > qg0) sacc[nf][0] = -INFINITY;
                if (cb + 1 > qg0) sacc[nf][1] = -INFINITY;
                if (cb     > qg1) sacc[nf][2] = -INFINITY;
                if (cb + 1 > qg1) sacc[nf][3] = -INFINITY;
            }
        }

        float mn0 = sacc[0][0], mn1 = sacc[0][2];
        #pragma unroll
        for (int nf = 0; nf < 8; nf++) {
            mn0 = fmaxf(mn0, fmaxf(sacc[nf][0], sacc[nf][1]));
            mn1 = fmaxf(mn1, fmaxf(sacc[nf][2], sacc[nf][3]));
        }
        mn0 = fmaxf(mn0, __shfl_xor_sync(0xffffffffu, mn0, 1));
        mn0 = fmaxf(mn0, __shfl_xor_sync(0xffffffffu, mn0, 2));
        mn1 = fmaxf(mn1, __shfl_xor_sync(0xffffffffu, mn1, 1));
        mn1 = fmaxf(mn1, __shfl_xor_sync(0xffffffffu, mn1, 2));
        mn0 = fmaxf(mr0, mn0);
        mn1 = fmaxf(mr1, mn1);

        const float cr0 = fexp2(mr0 - mn0);
        const float cr1 = fexp2(mr1 - mn1);
        mr0 = mn0; mr1 = mn1;
        #pragma unroll
        for (int nf = 0; nf < 8; nf++) {
            o[nf][0] *= cr0; o[nf][1] *= cr0;
            o[nf][2] *= cr1; o[nf][3] *= cr1;
        }
        ol[0] *= cr0; ol[1] *= cr0; ol[2] *= cr1; ol[3] *= cr1;

        // P = exp2(S - m) directly into A-fragments (no smem round-trip).
        // C-frag (g,2tig / g+8,2tig) == A-frag (row, k) layout.
        uint32_t pa[4][4];
        #pragma unroll
        for (int kf = 0; kf < 4; kf++) {
            const int e = 2 * kf, d = 2 * kf + 1;
            pa[kf][0] = ex2_h2(pack_h2(sacc[e][0] - mn0, sacc[e][1] - mn0));
            pa[kf][1] = ex2_h2(pack_h2(sacc[e][2] - mn1, sacc[e][3] - mn1));
            pa[kf][2] = ex2_h2(pack_h2(sacc[d][0] - mn0, sacc[d][1] - mn0));
            pa[kf][3] = ex2_h2(pack_h2(sacc[d][2] - mn1, sacc[d][3] - mn1));
        }

        // O += P @ V ; l += P @ 1  (V [t][d] via ldmatrix.trans)
        #pragma unroll
        for (int kf = 0; kf < 4; kf++) {
            #pragma unroll
            for (int p = 0; p < 4; p++) {
                uint32_t b[2][2];
                LDSM_X4_T(b[0][0], b[0][1], b[1][0], b[1][1],
                          Vs_u + ksoff + ((kf * 16 + vt_row) * FPS + p * 16 + vt_col) * 2);
                mma_f16(o[2 * p],     pa[kf], b[0]);
                mma_f16(o[2 * p + 1], pa[kf], b[1]);
            }
            mma_f16(ol, pa[kf], ONES);
        }
    }

    // Epilogue: normalize, write half to g_Ah [b, t, h*64+d]
    const float i0 = 1.f / ol[0], i1 = 1.f / ol[2];
    const int bb = bh >> 4, h = bh & 15;
    __half* A0 = g_Ah + ((size_t)(bb * SEQ) + qg0) * DMODEL + h * HDIM;
    __half* A1 = g_Ah + ((size_t)(bb * SEQ) + qg1) * DMODEL + h * HDIM;
    #pragma unroll
    for (int nf = 0; nf < 8; nf++) {
        *(uint32_t*)(A0 + nf * 8 + 2 * tig) = pack_h2(o[nf][0] * i0, o[nf][1] * i0);
        *(uint32_t*)(A1 + nf * 8 + 2 * tig) = pack_h2(o[nf][2] * i1, o[nf][3] * i1);
    }
    #undef ISSUE_KV
}

// ---------------------------------------------------------------------------
extern "C" void kernel_launch(void* const* d_in, const int* in_sizes, int n_in,
                              void* d_out, int out_size)
{
    const float* x  = (const float*)d_in[0];
    const float* Wq = (const float*)d_in[2];
    const float* bq = (const float*)d_in[3];
    const float* Wk = (const float*)d_in[4];
    const float* bk = (const float*)d_in[5];
    const float* Wv = (const float*)d_in[6];
    const float* bv = (const float*)d_in[7];
    const float* Wo = (const float*)d_in[8];
    const float* bo = (const float*)d_in[9];
    float* out = (float*)d_out;

    __half *Qp, *Kp, *Vp, *Ap, *Wt, *Xh;
    cudaGetSymbolAddress((void**)&Qp, g_Qh);
    cudaGetSymbolAddress((void**)&Kp, g_Kh);
    cudaGetSymbolAddress((void**)&Vp, g_Vh);
    cudaGetSymbolAddress((void**)&Ap, g_Ah);
    cudaGetSymbolAddress((void**)&Wt, g_Wth);
    cudaGetSymbolAddress((void**)&Xh, g_Xh);

    cudaFuncSetAttribute(flash_mma, cudaFuncAttributeMaxDynamicSharedMemorySize,
                         FLASH_SMEM);
    cudaFuncSetAttribute(gemm_pipe<1>, cudaFuncAttributeMaxDynamicSharedMemorySize,
                         GP_SMEM);
    cudaFuncSetAttribute(gemm_pipe<0>, cudaFuncAttributeMaxDynamicSharedMemorySize,
                         GP_SMEM);

    tohalf_kernel<<<(MROWS * DMODEL) / (256 * 8), 256>>>((const float4*)x, (uint4*)Xh);
    dim3 tgrid(32, 32, 4), tblk(32, 8);
    transpose4_kernel<<<tgrid, tblk>>>(Wq, Wk, Wv, Wo, Wt);

    // Fused QKV projection (z selects weight/bias/output; Q pre-scaled)
    dim3 qkvgrid(DMODEL / 128, MROWS / 128, 3);   // (8, 64, 3)
    gemm_pipe<1><<<qkvgrid, 256, GP_SMEM>>>(Xh, Wt, bq, bk, bv, Qp, Kp, Vp);

    dim3 fgrid(SEQ / 128, BATCH * NHEADS);        // (16, 64)
    flash_mma<<<fgrid, 256, FLASH_SMEM>>>();

    dim3 ogrid(DMODEL / 128, MROWS / 128, 1);
    gemm_pipe<0><<<ogrid, 256, GP_SMEM>>>(Ap, Wt + 3u * 1024u * 1024u,
                                          bo, bo, bo, out, out, out);
}